// round 8
// baseline (speedup 1.0000x reference)
#include <cuda_runtime.h>

#define BATCH     16384
#define QSEQ      1204
#define FDIM      7
#define NCHUNKS   120
#define NOFF      5
#define WINSZ     10
#define NCAT      600
#define H1DIM     128
#define H2DIM     32
#define ODIM      2

// pipeline chunking
#define PCHUNKS       4
#define ROWS_PER_CH   (BATCH / PCHUNKS)       // 4096

// cat scratch, k-major, each value duplicated: g_cat2[k*BATCH + b] = (v, v)
__device__ float2 g_cat2[(size_t)NCAT * BATCH];
// layer-A partials: [khalf][rowgroup][r][j]  (pre-bias, pre-relu)
__device__ float g_part[2][512][32][128];

// ---------------------------------------------------------------------------
__device__ __forceinline__ unsigned long long ffma2(unsigned long long a,
                                                    unsigned long long b,
                                                    unsigned long long c) {
    unsigned long long d;
    asm("fma.rn.f32x2 %0, %1, %2, %3;" : "=l"(d) : "l"(a), "l"(b), "l"(c));
    return d;
}
__device__ __forceinline__ void cp_async16(void* smem_dst, const void* gsrc) {
    unsigned s = (unsigned)__cvta_generic_to_shared(smem_dst);
    asm volatile("cp.async.ca.shared.global [%0], [%1], 16;\n" :: "r"(s), "l"(gsrc));
}
__device__ __forceinline__ void cp_commit() {
    asm volatile("cp.async.commit_group;\n" ::: "memory");
}
__device__ __forceinline__ void cp_wait0() {
    asm volatile("cp.async.wait_group 0;\n" ::: "memory");
}

// ===========================================================================
// Kernel 1: dot-7 + windowed max pool (smem-staged, coalesced) — per chunk
// ===========================================================================
#define K1_ROWS 8
__global__ __launch_bounds__(256)
void pool_kernel(const float* __restrict__ x,
                 const float* __restrict__ w_step,
                 const float* __restrict__ b_step,
                 int row_off)
{
    __shared__ float sm_out[K1_ROWS][QSEQ];

    const int tid = threadIdx.x;
    const size_t b0 = (size_t)row_off + (size_t)blockIdx.x * K1_ROWS;

    float ws[FDIM];
#pragma unroll
    for (int f = 0; f < FDIM; ++f) ws[f] = __ldg(&w_step[f]);
    const float bs = __ldg(b_step);

    for (int it = tid; it < K1_ROWS * 301; it += 256) {
        const int r  = it / 301;
        const int qd = it - r * 301;
        const float4* p = (const float4*)(x + (b0 + (size_t)r) * (QSEQ * FDIM) + qd * 28);
        float v[28];
#pragma unroll
        for (int i = 0; i < 7; ++i) {
            float4 t = p[i];
            v[i*4+0] = t.x; v[i*4+1] = t.y; v[i*4+2] = t.z; v[i*4+3] = t.w;
        }
#pragma unroll
        for (int qq = 0; qq < 4; ++qq) {
            float acc = bs;
#pragma unroll
            for (int f = 0; f < FDIM; ++f)
                acc = fmaf(v[qq*FDIM + f], ws[f], acc);
            sm_out[r][qd*4 + qq] = acc;
        }
    }
    __syncthreads();

    for (int it = tid; it < K1_ROWS * NCHUNKS; it += 256) {
        const int r = it & (K1_ROWS - 1);
        const int i = it >> 3;
        const float* o = &sm_out[r][i * WINSZ];
        float v[14];
#pragma unroll
        for (int j = 0; j < 14; ++j) v[j] = o[j];

        float common = v[4];
#pragma unroll
        for (int j = 5; j < 10; ++j) common = fmaxf(common, v[j]);
        const float P1 = v[10];
        const float P2 = fmaxf(P1, v[11]);
        const float P3 = fmaxf(P2, v[12]);
        const float P4 = fmaxf(P3, v[13]);
        const float T3 = v[3];
        const float T2 = fmaxf(v[2], T3);
        const float T1 = fmaxf(v[1], T2);
        const float T0 = fmaxf(v[0], T1);

        float m[5];
        m[0] = fmaxf(common, T0);
        m[1] = fmaxf(fmaxf(common, T1), P1);
        m[2] = fmaxf(fmaxf(common, T2), P2);
        m[3] = fmaxf(fmaxf(common, T3), P3);
        m[4] = fmaxf(common, P4);

        const size_t base = b0 + (size_t)r;
        const size_t c0 = (size_t)(i * NOFF) * BATCH + base;
#pragma unroll
        for (int o2 = 0; o2 < NOFF; ++o2) {
            float2 vv; vv.x = m[o2]; vv.y = m[o2];
            g_cat2[c0 + (size_t)o2 * BATCH] = vv;
        }
    }
}

// ===========================================================================
// Kernel 2a: layer A, split-K x2, per chunk. grid = rowgroups*2.
// 128 thr; thread = 8 neurons x 4 rows; 16 FFMA2 + 4 LDS.128 per k.
// ===========================================================================
#define NROWS  32
#define KHALF  300
#define KT     20
#define NTILE  15                       // 15*20 = 300
#define WA_TF  (KT * H1DIM)             // 2560 floats
#define CT_TF  (KT * NROWS * 2)         // 1280 floats (duplicated)
#define BUF_F  (WA_TF + CT_TF)          // 3840 floats

__global__ __launch_bounds__(128, 7)
void mlpA_kernel(const float* __restrict__ wA, int rg_off)
{
    __shared__ float smem[2 * BUF_F];   // 30720 B

    const int tid = threadIdx.x;
    const int rg  = rg_off + (blockIdx.x >> 1);
    const int kh  = blockIdx.x & 1;
    const size_t b0 = (size_t)rg * NROWS;

    const float* wAh = wA + (size_t)kh * KHALF * H1DIM;
    const size_t kbase = (size_t)kh * KHALF;

    const int jq = tid & 15;            // j0 = 8*jq
    const int rs = tid >> 4;            // r0 = 4*rs
    const int j0 = jq * 8;
    const int r0 = rs * 4;

    // ---- prologue: tile 0 ----
    {
        float* wbuf = smem;
        float* cbuf = smem + WA_TF;
#pragma unroll
        for (int i = 0; i < 5; ++i) {               // 640 float4
            const int idx = tid + i * 128;
            cp_async16(wbuf + idx * 4, wAh + idx * 4);
        }
        for (int idx = tid; idx < 320; idx += 128) { // 320 16B chunks
            const int kk = idx >> 4;
            const int rp = idx & 15;
            cp_async16(cbuf + kk * (NROWS * 2) + rp * 4,
                       &g_cat2[(kbase + kk) * BATCH + b0 + rp * 2]);
        }
        cp_commit();
    }

    unsigned long long acc[4][4];
#pragma unroll
    for (int n = 0; n < 4; ++n)
#pragma unroll
        for (int r = 0; r < 4; ++r) acc[n][r] = 0ULL;

    for (int t = 0; t < NTILE; ++t) {
        cp_wait0();
        __syncthreads();
        if (t + 1 < NTILE) {
            float* wbuf = smem + ((t + 1) & 1) * BUF_F;
            float* cbuf = wbuf + WA_TF;
            const float* wsrc = wAh + (size_t)(t + 1) * WA_TF;
            const size_t kof = kbase + (size_t)(t + 1) * KT;
#pragma unroll
            for (int i = 0; i < 5; ++i) {
                const int idx = tid + i * 128;
                cp_async16(wbuf + idx * 4, wsrc + idx * 4);
            }
            for (int idx = tid; idx < 320; idx += 128) {
                const int kk = idx >> 4;
                const int rp = idx & 15;
                cp_async16(cbuf + kk * (NROWS * 2) + rp * 4,
                           &g_cat2[(kof + kk) * BATCH + b0 + rp * 2]);
            }
            cp_commit();
        }

        const float* wt = smem + (t & 1) * BUF_F + j0;
        const float* ct = smem + (t & 1) * BUF_F + WA_TF + r0 * 2;
#pragma unroll 4
        for (int kk = 0; kk < KT; ++kk) {
            const ulonglong2 w0 = *(const ulonglong2*)(wt + kk * H1DIM);       // neurons j0..j0+3
            const ulonglong2 w1 = *(const ulonglong2*)(wt + kk * H1DIM + 4);   // neurons j0+4..j0+7
            const ulonglong2 c0 = *(const ulonglong2*)(ct + kk * (NROWS * 2));     // rows r0,r0+1 (dup)
            const ulonglong2 c1 = *(const ulonglong2*)(ct + kk * (NROWS * 2) + 4); // rows r0+2,r0+3
            acc[0][0] = ffma2(w0.x, c0.x, acc[0][0]);
            acc[1][0] = ffma2(w0.y, c0.x, acc[1][0]);
            acc[2][0] = ffma2(w1.x, c0.x, acc[2][0]);
            acc[3][0] = ffma2(w1.y, c0.x, acc[3][0]);
            acc[0][1] = ffma2(w0.x, c0.y, acc[0][1]);
            acc[1][1] = ffma2(w0.y, c0.y, acc[1][1]);
            acc[2][1] = ffma2(w1.x, c0.y, acc[2][1]);
            acc[3][1] = ffma2(w1.y, c0.y, acc[3][1]);
            acc[0][2] = ffma2(w0.x, c1.x, acc[0][2]);
            acc[1][2] = ffma2(w0.y, c1.x, acc[1][2]);
            acc[2][2] = ffma2(w1.x, c1.x, acc[2][2]);
            acc[3][2] = ffma2(w1.y, c1.x, acc[3][2]);
            acc[0][3] = ffma2(w0.x, c1.y, acc[0][3]);
            acc[1][3] = ffma2(w0.y, c1.y, acc[1][3]);
            acc[2][3] = ffma2(w1.x, c1.y, acc[2][3]);
            acc[3][3] = ffma2(w1.y, c1.y, acc[3][3]);
        }
    }

    // ---- epilogue: coalesced STG.128 of partials, layout [r][j] ----
    float* dst = &g_part[kh][rg][0][0];
#pragma unroll
    for (int r = 0; r < 4; ++r) {
        ulonglong2 s0, s1;
        s0.x = acc[0][r]; s0.y = acc[1][r];      // j0..j0+3
        s1.x = acc[2][r]; s1.y = acc[3][r];      // j0+4..j0+7
        *(ulonglong2*)&dst[(r0 + r) * H1DIM + j0]     = s0;
        *(ulonglong2*)&dst[(r0 + r) * H1DIM + j0 + 4] = s1;
    }
}

// ===========================================================================
// Kernel 2b: combine halves + bias/relu, then layers B and C — per chunk.
// ===========================================================================
#define H1PAD 33
__global__ __launch_bounds__(256)
void mlpB_kernel(const float* __restrict__ bA,
                 const float* __restrict__ wB,
                 const float* __restrict__ bB,
                 const float* __restrict__ wC,
                 const float* __restrict__ bC,
                 float* __restrict__ out,
                 int rg_off)
{
    __shared__ float h1[H1DIM * H1PAD];      // [j][r], padded
    __shared__ float h2[NROWS * H2DIM];

    const int tid = threadIdx.x;
    const int rg  = rg_off + blockIdx.x;
    const size_t b0 = (size_t)rg * NROWS;

    const float* p0 = &g_part[0][rg][0][0];
    const float* p1 = &g_part[1][rg][0][0];

    // sum halves + bias + relu, transpose into h1[j][r]
    for (int idx = tid; idx < (NROWS * H1DIM) / 4; idx += 256) {
        const int r  = idx >> 5;
        const int j4 = (idx & 31) * 4;
        const float4 a  = *(const float4*)&p0[r * H1DIM + j4];
        const float4 b  = *(const float4*)&p1[r * H1DIM + j4];
        const float4 bb = *(const float4*)&bA[j4];
        h1[(j4 + 0) * H1PAD + r] = fmaxf(a.x + b.x + bb.x, 0.0f);
        h1[(j4 + 1) * H1PAD + r] = fmaxf(a.y + b.y + bb.y, 0.0f);
        h1[(j4 + 2) * H1PAD + r] = fmaxf(a.z + b.z + bb.z, 0.0f);
        h1[(j4 + 3) * H1PAD + r] = fmaxf(a.w + b.w + bb.w, 0.0f);
    }
    __syncthreads();

    // layer B: thread = (m, 4 rows)
    {
        const int m  = tid & 31;
        const int rb = (tid >> 5) * 4;
        float s0 = 0, s1 = 0, s2 = 0, s3 = 0;
#pragma unroll 4
        for (int j = 0; j < H1DIM; ++j) {
            const float wb = __ldg(&wB[j * H2DIM + m]);
            const float* hj = &h1[j * H1PAD + rb];
            s0 = fmaf(hj[0], wb, s0);
            s1 = fmaf(hj[1], wb, s1);
            s2 = fmaf(hj[2], wb, s2);
            s3 = fmaf(hj[3], wb, s3);
        }
        const float bm = __ldg(&bB[m]);
        h2[(rb + 0) * H2DIM + m] = fmaxf(s0 + bm, 0.0f);
        h2[(rb + 1) * H2DIM + m] = fmaxf(s1 + bm, 0.0f);
        h2[(rb + 2) * H2DIM + m] = fmaxf(s2 + bm, 0.0f);
        h2[(rb + 3) * H2DIM + m] = fmaxf(s3 + bm, 0.0f);
    }
    __syncthreads();

    // layer C
    if (tid < NROWS * ODIM) {
        const int r = tid >> 1;
        const int c = tid & 1;
        float s = __ldg(&bC[c]);
#pragma unroll
        for (int m = 0; m < H2DIM; ++m)
            s = fmaf(h2[r * H2DIM + m], __ldg(&wC[m * ODIM + c]), s);
        out[(b0 + (size_t)r) * ODIM + c] = s;
    }
}

// ===========================================================================
// Launch: chunked two-stream pipeline.  pool(c) on stream 0; mlp(c) on forked
// stream s1 gated by event after pool(c). Join back before return (required
// for graph capture legality). Streams/events are host objects, created once;
// identical work is enqueued on every call.
// ===========================================================================
extern "C" void kernel_launch(void* const* d_in, const int* in_sizes, int n_in,
                              void* d_out, int out_size)
{
    const float* x      = (const float*)d_in[0];
    const float* w_step = (const float*)d_in[1];
    const float* b_step = (const float*)d_in[2];
    const float* wA     = (const float*)d_in[3];
    const float* bA     = (const float*)d_in[4];
    const float* wB     = (const float*)d_in[5];
    const float* bB     = (const float*)d_in[6];
    const float* wC     = (const float*)d_in[7];
    const float* bC     = (const float*)d_in[8];
    float* out          = (float*)d_out;

    static cudaStream_t s1 = nullptr;
    static cudaEvent_t  evFork = nullptr;
    static cudaEvent_t  evPool[PCHUNKS];
    static cudaEvent_t  evJoin = nullptr;
    if (s1 == nullptr) {
        cudaStreamCreateWithFlags(&s1, cudaStreamNonBlocking);
        cudaEventCreateWithFlags(&evFork, cudaEventDisableTiming);
        for (int c = 0; c < PCHUNKS; ++c)
            cudaEventCreateWithFlags(&evPool[c], cudaEventDisableTiming);
        cudaEventCreateWithFlags(&evJoin, cudaEventDisableTiming);
    }

    const int poolCtas = ROWS_PER_CH / K1_ROWS;          // 512
    const int rgPerCh  = ROWS_PER_CH / NROWS;            // 128

    // fork s1 off the capture (default) stream
    cudaEventRecord(evFork, 0);
    cudaStreamWaitEvent(s1, evFork, 0);

    for (int c = 0; c < PCHUNKS; ++c) {
        pool_kernel<<<poolCtas, 256, 0, 0>>>(x, w_step, b_step, c * ROWS_PER_CH);
        cudaEventRecord(evPool[c], 0);

        cudaStreamWaitEvent(s1, evPool[c], 0);
        mlpA_kernel<<<rgPerCh * 2, 128, 0, s1>>>(wA, c * rgPerCh);
        mlpB_kernel<<<rgPerCh, 256, 0, s1>>>(bA, wB, bB, wC, bC, out, c * rgPerCh);
    }

    // join s1 back into the capture stream
    cudaEventRecord(evJoin, s1);
    cudaStreamWaitEvent(0, evJoin, 0);
}

// round 9
// speedup vs baseline: 1.3363x; 1.3363x over previous
#include <cuda_runtime.h>

#define BATCH     16384
#define QSEQ      1204
#define FDIM      7
#define NCHUNKS   120
#define NOFF      5
#define WINSZ     10
#define NCAT      600
#define H1DIM     128
#define H2DIM     32
#define ODIM      2

// cat scratch, k-major, each value duplicated: g_cat2[k*BATCH + b] = (v, v)
__device__ float2 g_cat2[(size_t)NCAT * BATCH];

// ---------------------------------------------------------------------------
__device__ __forceinline__ void unpack2(unsigned long long v, float& lo, float& hi) {
    asm("mov.b64 {%0, %1}, %2;" : "=f"(lo), "=f"(hi) : "l"(v));
}
__device__ __forceinline__ unsigned long long ffma2(unsigned long long a,
                                                    unsigned long long b,
                                                    unsigned long long c) {
    unsigned long long d;
    asm("fma.rn.f32x2 %0, %1, %2, %3;" : "=l"(d) : "l"(a), "l"(b), "l"(c));
    return d;
}
__device__ __forceinline__ void cp_async16(void* smem_dst, const void* gsrc) {
    unsigned s = (unsigned)__cvta_generic_to_shared(smem_dst);
    asm volatile("cp.async.ca.shared.global [%0], [%1], 16;\n" :: "r"(s), "l"(gsrc));
}
__device__ __forceinline__ void cp_commit() {
    asm volatile("cp.async.commit_group;\n" ::: "memory");
}
__device__ __forceinline__ void cp_wait2() {
    asm volatile("cp.async.wait_group 2;\n" ::: "memory");
}

// ===========================================================================
// Kernel 1: dot-7 + windowed max pool (R7 version — known good, 62% DRAM)
// ===========================================================================
#define K1_ROWS 8
__global__ __launch_bounds__(256)
void pool_kernel(const float* __restrict__ x,
                 const float* __restrict__ w_step,
                 const float* __restrict__ b_step)
{
    __shared__ float sm_out[K1_ROWS][QSEQ];

    const int tid = threadIdx.x;
    const size_t b0 = (size_t)blockIdx.x * K1_ROWS;

    float ws[FDIM];
#pragma unroll
    for (int f = 0; f < FDIM; ++f) ws[f] = __ldg(&w_step[f]);
    const float bs = __ldg(b_step);

    for (int it = tid; it < K1_ROWS * 301; it += 256) {
        const int r  = it / 301;
        const int qd = it - r * 301;
        const float4* p = (const float4*)(x + (b0 + (size_t)r) * (QSEQ * FDIM) + qd * 28);
        float v[28];
#pragma unroll
        for (int i = 0; i < 7; ++i) {
            float4 t = p[i];
            v[i*4+0] = t.x; v[i*4+1] = t.y; v[i*4+2] = t.z; v[i*4+3] = t.w;
        }
#pragma unroll
        for (int qq = 0; qq < 4; ++qq) {
            float acc = bs;
#pragma unroll
            for (int f = 0; f < FDIM; ++f)
                acc = fmaf(v[qq*FDIM + f], ws[f], acc);
            sm_out[r][qd*4 + qq] = acc;
        }
    }
    __syncthreads();

    for (int it = tid; it < K1_ROWS * NCHUNKS; it += 256) {
        const int r = it & (K1_ROWS - 1);
        const int i = it >> 3;
        const float* o = &sm_out[r][i * WINSZ];
        float v[14];
#pragma unroll
        for (int j = 0; j < 14; ++j) v[j] = o[j];

        float common = v[4];
#pragma unroll
        for (int j = 5; j < 10; ++j) common = fmaxf(common, v[j]);
        const float P1 = v[10];
        const float P2 = fmaxf(P1, v[11]);
        const float P3 = fmaxf(P2, v[12]);
        const float P4 = fmaxf(P3, v[13]);
        const float T3 = v[3];
        const float T2 = fmaxf(v[2], T3);
        const float T1 = fmaxf(v[1], T2);
        const float T0 = fmaxf(v[0], T1);

        float m[5];
        m[0] = fmaxf(common, T0);
        m[1] = fmaxf(fmaxf(common, T1), P1);
        m[2] = fmaxf(fmaxf(common, T2), P2);
        m[3] = fmaxf(fmaxf(common, T3), P3);
        m[4] = fmaxf(common, P4);

        const size_t base = b0 + (size_t)r;
        const size_t c0 = (size_t)(i * NOFF) * BATCH + base;
#pragma unroll
        for (int o2 = 0; o2 < NOFF; ++o2) {
            float2 vv; vv.x = m[o2]; vv.y = m[o2];
            g_cat2[c0 + (size_t)o2 * BATCH] = vv;
        }
    }
}

// ===========================================================================
// Kernel 2: MLP. 256 thr, 32 rows/CTA, grid 512 (single wave at 4 CTAs/SM).
// 3-stage cp.async pipeline streaming BOTH wA and dup-cat tiles.
// Thread = 4 neurons x 4 rows: 3 LDS.128 + 8 FFMA2 per k, no packing.
// ===========================================================================
#define NROWS  32
#define KT     24
#define NTILE  25                       // 25*24 = 600
#define WA_TF  (KT * H1DIM)             // 3072 floats
#define CT_TF  (KT * NROWS * 2)         // 1536 floats (duplicated)
#define BUF_F  (WA_TF + CT_TF)          // 4608 floats = 18432 B
#define NBUF   3
#define SM_BYTES (NBUF * BUF_F * 4)     // 55296 B

__global__ __launch_bounds__(256, 4)
void mlp_kernel(const float* __restrict__ wA,
                const float* __restrict__ bA,
                const float* __restrict__ wB,
                const float* __restrict__ bB,
                const float* __restrict__ wC,
                const float* __restrict__ bC,
                float* __restrict__ out)
{
    extern __shared__ float smem[];
    // after the mainloop the buffers are dead; alias h1/h2:
    float* sm_h1 = smem;                        // 128*33 = 4224 floats (padded)
    float* sm_h2 = smem + H1DIM * 33;           // 1024 floats

    const int tid = threadIdx.x;
    const size_t b0 = (size_t)blockIdx.x * NROWS;

    const int jq = tid & 31;            // j0 = 4*jq
    const int rs = tid >> 5;            // r0 = 4*rs
    const int j0 = jq * 4;
    const int r0 = rs * 4;

    // ---- tile loader: wA tile (768 float4) + dup-cat tile (384 chunks) ----
    auto load_tile = [&](int t) {
        float* buf  = smem + (t % NBUF) * BUF_F;
        float* cbuf = buf + WA_TF;
        const float* wsrc = wA + (size_t)t * WA_TF;
        const size_t kof = (size_t)t * KT;
#pragma unroll
        for (int i = 0; i < 3; ++i) {
            const int idx = tid + i * 256;
            cp_async16(buf + idx * 4, wsrc + idx * 4);
        }
        {
            int idx = tid;                       // 384 chunks: 256 + 128
            {
                const int kk = idx >> 4, rp = idx & 15;
                cp_async16(cbuf + kk * 64 + rp * 4,
                           &g_cat2[(kof + kk) * BATCH + b0 + rp * 2]);
            }
            idx += 256;
            if (idx < 384) {
                const int kk = idx >> 4, rp = idx & 15;
                cp_async16(cbuf + kk * 64 + rp * 4,
                           &g_cat2[(kof + kk) * BATCH + b0 + rp * 2]);
            }
        }
        cp_commit();
    };

    // ---- prologue: tiles 0 and 1 in flight ----
    load_tile(0);
    load_tile(1);

    unsigned long long acc[2][4];       // [neuron-pair][row]
#pragma unroll
    for (int n = 0; n < 2; ++n)
#pragma unroll
        for (int r = 0; r < 4; ++r) acc[n][r] = 0ULL;

    for (int t = 0; t < NTILE; ++t) {
        __syncthreads();                 // all threads done with tile t-1 (buffer (t+2)%3 free)
        if (t + 2 < NTILE) load_tile(t + 2);
        else               cp_commit();  // empty group keeps pending count uniform
        cp_wait2();                      // tile t's group complete (<=2 pending)
        __syncthreads();                 // tile t visible to all threads

        const float* wt = smem + (t % NBUF) * BUF_F + j0;
        const float* ct = smem + (t % NBUF) * BUF_F + WA_TF + r0 * 2;
#pragma unroll 4
        for (int kk = 0; kk < KT; ++kk) {
            const ulonglong2 w2 = *(const ulonglong2*)(wt + kk * H1DIM);   // neurons j0..j0+3
            const ulonglong2 c0 = *(const ulonglong2*)(ct + kk * 64);      // rows r0,r0+1 (dup)
            const ulonglong2 c1 = *(const ulonglong2*)(ct + kk * 64 + 4);  // rows r0+2,r0+3
            acc[0][0] = ffma2(w2.x, c0.x, acc[0][0]);
            acc[1][0] = ffma2(w2.y, c0.x, acc[1][0]);
            acc[0][1] = ffma2(w2.x, c0.y, acc[0][1]);
            acc[1][1] = ffma2(w2.y, c0.y, acc[1][1]);
            acc[0][2] = ffma2(w2.x, c1.x, acc[0][2]);
            acc[1][2] = ffma2(w2.y, c1.x, acc[1][2]);
            acc[0][3] = ffma2(w2.x, c1.y, acc[0][3]);
            acc[1][3] = ffma2(w2.y, c1.y, acc[1][3]);
        }
    }

    const float4 b4 = *(const float4*)&bA[j0];
    __syncthreads();                     // buffers dead; safe to alias h1

    // ---- epilogue: h1[j*33 + r] = relu(acc + bias) ----
    {
        float lo, hi;
#pragma unroll
        for (int n = 0; n < 2; ++n) {
            const float bl = n ? b4.z : b4.x;
            const float bh = n ? b4.w : b4.y;
#pragma unroll
            for (int r = 0; r < 4; ++r) {
                unpack2(acc[n][r], lo, hi);
                sm_h1[(j0 + 2*n + 0) * 33 + r0 + r] = fmaxf(lo + bl, 0.0f);
                sm_h1[(j0 + 2*n + 1) * 33 + r0 + r] = fmaxf(hi + bh, 0.0f);
            }
        }
    }
    __syncthreads();

    // ---- Layer B: h2[r][m] = relu(sum_j h1[j][r]*wB[j][m] + bB[m]) ----
    {
        const int m  = tid & 31;
        const int rb = (tid >> 5) * 4;
        float s0 = 0, s1 = 0, s2 = 0, s3 = 0;
#pragma unroll 4
        for (int j = 0; j < H1DIM; ++j) {
            const float wb = __ldg(&wB[j * H2DIM + m]);
            const float* hj = &sm_h1[j * 33 + rb];
            s0 = fmaf(hj[0], wb, s0);
            s1 = fmaf(hj[1], wb, s1);
            s2 = fmaf(hj[2], wb, s2);
            s3 = fmaf(hj[3], wb, s3);
        }
        const float bm = __ldg(&bB[m]);
        sm_h2[(rb + 0) * H2DIM + m] = fmaxf(s0 + bm, 0.0f);
        sm_h2[(rb + 1) * H2DIM + m] = fmaxf(s1 + bm, 0.0f);
        sm_h2[(rb + 2) * H2DIM + m] = fmaxf(s2 + bm, 0.0f);
        sm_h2[(rb + 3) * H2DIM + m] = fmaxf(s3 + bm, 0.0f);
    }
    __syncthreads();

    // ---- Layer C ----
    if (tid < NROWS * ODIM) {
        const int r = tid >> 1;
        const int c = tid & 1;
        float s = __ldg(&bC[c]);
#pragma unroll
        for (int m = 0; m < H2DIM; ++m)
            s = fmaf(sm_h2[r * H2DIM + m], __ldg(&wC[m * ODIM + c]), s);
        out[(b0 + (size_t)r) * ODIM + c] = s;
    }
}

extern "C" void kernel_launch(void* const* d_in, const int* in_sizes, int n_in,
                              void* d_out, int out_size)
{
    const float* x      = (const float*)d_in[0];
    const float* w_step = (const float*)d_in[1];
    const float* b_step = (const float*)d_in[2];
    const float* wA     = (const float*)d_in[3];
    const float* bA     = (const float*)d_in[4];
    const float* wB     = (const float*)d_in[5];
    const float* bB     = (const float*)d_in[6];
    const float* wC     = (const float*)d_in[7];
    const float* bC     = (const float*)d_in[8];
    float* out          = (float*)d_out;

    cudaFuncSetAttribute(mlp_kernel, cudaFuncAttributeMaxDynamicSharedMemorySize, SM_BYTES);

    pool_kernel<<<BATCH / K1_ROWS, 256>>>(x, w_step, b_step);
    mlp_kernel<<<BATCH / NROWS, 256, SM_BYTES>>>(wA, bA, wB, bB, wC, bC, out);
}

// round 10
// speedup vs baseline: 1.6148x; 1.2085x over previous
#include <cuda_runtime.h>

#define BATCH     16384
#define QSEQ      1204
#define FDIM      7
#define NCHUNKS   120
#define NOFF      5
#define WINSZ     10
#define NCAT      600
#define H1DIM     128
#define H2DIM     32
#define ODIM      2

// cat scratch, k-major: g_cat[k*BATCH + b]
__device__ float g_cat[(size_t)NCAT * BATCH];

// ---------------------------------------------------------------------------
__device__ __forceinline__ unsigned long long pack2(float lo, float hi) {
    unsigned long long r;
    asm("mov.b64 %0, {%1, %2};" : "=l"(r) : "f"(lo), "f"(hi));
    return r;
}
__device__ __forceinline__ void unpack2(unsigned long long v, float& lo, float& hi) {
    asm("mov.b64 {%0, %1}, %2;" : "=f"(lo), "=f"(hi) : "l"(v));
}
__device__ __forceinline__ unsigned long long ffma2(unsigned long long a,
                                                    unsigned long long b,
                                                    unsigned long long c) {
    unsigned long long d;
    asm("fma.rn.f32x2 %0, %1, %2, %3;" : "=l"(d) : "l"(a), "l"(b), "l"(c));
    return d;
}
__device__ __forceinline__ void cp_async16(void* smem_dst, const void* gsrc) {
    unsigned s = (unsigned)__cvta_generic_to_shared(smem_dst);
    asm volatile("cp.async.ca.shared.global [%0], [%1], 16;\n" :: "r"(s), "l"(gsrc));
}
__device__ __forceinline__ void cp_commit() {
    asm volatile("cp.async.commit_group;\n" ::: "memory");
}
__device__ __forceinline__ void cp_wait2() {
    asm volatile("cp.async.wait_group 2;\n" ::: "memory");
}

// ===========================================================================
// Kernel 1: dot-7 + windowed max pool (known good; plain float stores)
// ===========================================================================
#define K1_ROWS 8
__global__ __launch_bounds__(256)
void pool_kernel(const float* __restrict__ x,
                 const float* __restrict__ w_step,
                 const float* __restrict__ b_step)
{
    __shared__ float sm_out[K1_ROWS][QSEQ];

    const int tid = threadIdx.x;
    const size_t b0 = (size_t)blockIdx.x * K1_ROWS;

    float ws[FDIM];
#pragma unroll
    for (int f = 0; f < FDIM; ++f) ws[f] = __ldg(&w_step[f]);
    const float bs = __ldg(b_step);

    for (int it = tid; it < K1_ROWS * 301; it += 256) {
        const int r  = it / 301;
        const int qd = it - r * 301;
        const float4* p = (const float4*)(x + (b0 + (size_t)r) * (QSEQ * FDIM) + qd * 28);
        float v[28];
#pragma unroll
        for (int i = 0; i < 7; ++i) {
            float4 t = p[i];
            v[i*4+0] = t.x; v[i*4+1] = t.y; v[i*4+2] = t.z; v[i*4+3] = t.w;
        }
#pragma unroll
        for (int qq = 0; qq < 4; ++qq) {
            float acc = bs;
#pragma unroll
            for (int f = 0; f < FDIM; ++f)
                acc = fmaf(v[qq*FDIM + f], ws[f], acc);
            sm_out[r][qd*4 + qq] = acc;
        }
    }
    __syncthreads();

    for (int it = tid; it < K1_ROWS * NCHUNKS; it += 256) {
        const int r = it & (K1_ROWS - 1);
        const int i = it >> 3;
        const float* o = &sm_out[r][i * WINSZ];
        float v[14];
#pragma unroll
        for (int j = 0; j < 14; ++j) v[j] = o[j];

        float common = v[4];
#pragma unroll
        for (int j = 5; j < 10; ++j) common = fmaxf(common, v[j]);
        const float P1 = v[10];
        const float P2 = fmaxf(P1, v[11]);
        const float P3 = fmaxf(P2, v[12]);
        const float P4 = fmaxf(P3, v[13]);
        const float T3 = v[3];
        const float T2 = fmaxf(v[2], T3);
        const float T1 = fmaxf(v[1], T2);
        const float T0 = fmaxf(v[0], T1);

        float m[5];
        m[0] = fmaxf(common, T0);
        m[1] = fmaxf(fmaxf(common, T1), P1);
        m[2] = fmaxf(fmaxf(common, T2), P2);
        m[3] = fmaxf(fmaxf(common, T3), P3);
        m[4] = fmaxf(common, P4);

        const size_t base = b0 + (size_t)r;
        const size_t c0 = (size_t)(i * NOFF) * BATCH + base;
#pragma unroll
        for (int o2 = 0; o2 < NOFF; ++o2)
            g_cat[c0 + (size_t)o2 * BATCH] = m[o2];
    }
}

// ===========================================================================
// Kernel 2: MLP. grid 128 (1 CTA/SM, single wave), 512 thr, 128 rows/CTA.
// Thread = (lane -> 4 rows, warp -> 8 neurons). Per warp-k: 6 LDS wavefronts
// for 32 FFMA2. 3-stage cp.async pipeline streams wA + cat k-tiles.
// ===========================================================================
#define NROWS  128
#define KT     40
#define NTILE  15                       // 15*40 = 600
#define WA_TF  (KT * H1DIM)             // 5120 floats
#define CT_TF  (KT * NROWS)             // 5120 floats
#define BUF_F  (WA_TF + CT_TF)          // 10240 floats = 40960 B
#define NBUF   3
#define SM_BYTES (NBUF * BUF_F * 4)     // 122880 B

__global__ __launch_bounds__(512, 1)
void mlp_kernel(const float* __restrict__ wA,
                const float* __restrict__ bA,
                const float* __restrict__ wB,
                const float* __restrict__ bB,
                const float* __restrict__ wC,
                const float* __restrict__ bC,
                float* __restrict__ out)
{
    extern __shared__ float smem[];
    float* sm_h1 = smem;                   // 128*128 floats, alias after mainloop
    float* sm_h2 = smem + H1DIM * NROWS;   // 128*32 floats

    const int tid  = threadIdx.x;
    const int lane = tid & 31;
    const int w    = tid >> 5;             // 0..15
    const int j0   = w * 8;                // 8 neurons per warp
    const int r0   = lane * 4;             // 4 rows per lane
    const size_t b0 = (size_t)blockIdx.x * NROWS;

    auto load_tile = [&](int t) {
        float* wbuf = smem + (t % NBUF) * BUF_F;
        float* cbuf = wbuf + WA_TF;
        const float* wsrc = wA + (size_t)t * WA_TF;
        const size_t kof = (size_t)t * KT;
        // wA: 1280 16B-chunks, linear
        for (int idx = tid; idx < WA_TF / 4; idx += 512)
            cp_async16(wbuf + idx * 4, wsrc + idx * 4);
        // cat: 1280 16B-chunks; [kk][128 rows]
        for (int idx = tid; idx < CT_TF / 4; idx += 512) {
            const int kk = idx >> 5;
            const int rc = idx & 31;
            cp_async16(cbuf + kk * NROWS + rc * 4,
                       &g_cat[(kof + kk) * BATCH + b0 + rc * 4]);
        }
        cp_commit();
    };

    load_tile(0);
    load_tile(1);

    // acc[n][p]: neuron j0+n, row pair (r0+2p, r0+2p+1)
    unsigned long long acc[8][2];
#pragma unroll
    for (int n = 0; n < 8; ++n) { acc[n][0] = 0ULL; acc[n][1] = 0ULL; }

    for (int t = 0; t < NTILE; ++t) {
        __syncthreads();                 // buffer (t+2)%3 fully consumed by all
        if (t + 2 < NTILE) load_tile(t + 2);
        else               cp_commit();  // empty group keeps wait count uniform
        cp_wait2();                      // tile t landed
        __syncthreads();                 // visible to all threads

        const float* wt = smem + (t % NBUF) * BUF_F + j0;
        const float* ct = smem + (t % NBUF) * BUF_F + WA_TF + r0;
#pragma unroll 4
        for (int kk = 0; kk < KT; ++kk) {
            // rows: one distinct LDS.128 per lane; pairs are FFMA2-ready
            const ulonglong2 c2 = *(const ulonglong2*)(ct + kk * NROWS);
            // neurons: two broadcast LDS.128 per warp
            const float4 w0 = *(const float4*)(wt + kk * H1DIM);
            const float4 w1 = *(const float4*)(wt + kk * H1DIM + 4);
            const unsigned long long s0 = pack2(w0.x, w0.x);
            const unsigned long long s1 = pack2(w0.y, w0.y);
            const unsigned long long s2 = pack2(w0.z, w0.z);
            const unsigned long long s3 = pack2(w0.w, w0.w);
            const unsigned long long s4 = pack2(w1.x, w1.x);
            const unsigned long long s5 = pack2(w1.y, w1.y);
            const unsigned long long s6 = pack2(w1.z, w1.z);
            const unsigned long long s7 = pack2(w1.w, w1.w);
            acc[0][0] = ffma2(c2.x, s0, acc[0][0]);
            acc[1][0] = ffma2(c2.x, s1, acc[1][0]);
            acc[2][0] = ffma2(c2.x, s2, acc[2][0]);
            acc[3][0] = ffma2(c2.x, s3, acc[3][0]);
            acc[4][0] = ffma2(c2.x, s4, acc[4][0]);
            acc[5][0] = ffma2(c2.x, s5, acc[5][0]);
            acc[6][0] = ffma2(c2.x, s6, acc[6][0]);
            acc[7][0] = ffma2(c2.x, s7, acc[7][0]);
            acc[0][1] = ffma2(c2.y, s0, acc[0][1]);
            acc[1][1] = ffma2(c2.y, s1, acc[1][1]);
            acc[2][1] = ffma2(c2.y, s2, acc[2][1]);
            acc[3][1] = ffma2(c2.y, s3, acc[3][1]);
            acc[4][1] = ffma2(c2.y, s4, acc[4][1]);
            acc[5][1] = ffma2(c2.y, s5, acc[5][1]);
            acc[6][1] = ffma2(c2.y, s6, acc[6][1]);
            acc[7][1] = ffma2(c2.y, s7, acc[7][1]);
        }
    }

    const float4 ba0 = *(const float4*)&bA[j0];
    const float4 ba1 = *(const float4*)&bA[j0 + 4];
    __syncthreads();                     // buffers dead; alias h1

    // ---- epilogue: h1[j][r] = relu(acc + bias), layout h1[j*128 + r] ----
    {
        const float bb[8] = {ba0.x, ba0.y, ba0.z, ba0.w, ba1.x, ba1.y, ba1.z, ba1.w};
        float lo, hi;
#pragma unroll
        for (int n = 0; n < 8; ++n) {
#pragma unroll
            for (int p = 0; p < 2; ++p) {
                unpack2(acc[n][p], lo, hi);
                sm_h1[(j0 + n) * NROWS + r0 + 2*p + 0] = fmaxf(lo + bb[n], 0.0f);
                sm_h1[(j0 + n) * NROWS + r0 + 2*p + 1] = fmaxf(hi + bb[n], 0.0f);
            }
        }
    }
    __syncthreads();

    // ---- Layer B: h2[r][m] = relu(sum_j h1[j][r]*wB[j][m] + bB[m]) ----
    {
        const int m  = tid & 31;
        const int rb = (tid >> 5) * 8;           // 16 warps x 8 rows = 128
        float s[8];
#pragma unroll
        for (int r = 0; r < 8; ++r) s[r] = 0.0f;
#pragma unroll 4
        for (int j = 0; j < H1DIM; ++j) {
            const float wb = __ldg(&wB[j * H2DIM + m]);
            const float4 h0 = *(const float4*)&sm_h1[j * NROWS + rb];
            const float4 h1v = *(const float4*)&sm_h1[j * NROWS + rb + 4];
            s[0] = fmaf(h0.x, wb, s[0]);
            s[1] = fmaf(h0.y, wb, s[1]);
            s[2] = fmaf(h0.z, wb, s[2]);
            s[3] = fmaf(h0.w, wb, s[3]);
            s[4] = fmaf(h1v.x, wb, s[4]);
            s[5] = fmaf(h1v.y, wb, s[5]);
            s[6] = fmaf(h1v.z, wb, s[6]);
            s[7] = fmaf(h1v.w, wb, s[7]);
        }
        const float bm = __ldg(&bB[m]);
#pragma unroll
        for (int r = 0; r < 8; ++r)
            sm_h2[(rb + r) * H2DIM + m] = fmaxf(s[r] + bm, 0.0f);
    }
    __syncthreads();

    // ---- Layer C ----
    if (tid < NROWS * ODIM) {
        const int r = tid >> 1;
        const int c = tid & 1;
        float s = __ldg(&bC[c]);
#pragma unroll
        for (int m = 0; m < H2DIM; ++m)
            s = fmaf(sm_h2[r * H2DIM + m], __ldg(&wC[m * ODIM + c]), s);
        out[(b0 + (size_t)r) * ODIM + c] = s;
    }
}

extern "C" void kernel_launch(void* const* d_in, const int* in_sizes, int n_in,
                              void* d_out, int out_size)
{
    const float* x      = (const float*)d_in[0];
    const float* w_step = (const float*)d_in[1];
    const float* b_step = (const float*)d_in[2];
    const float* wA     = (const float*)d_in[3];
    const float* bA     = (const float*)d_in[4];
    const float* wB     = (const float*)d_in[5];
    const float* bB     = (const float*)d_in[6];
    const float* wC     = (const float*)d_in[7];
    const float* bC     = (const float*)d_in[8];
    float* out          = (float*)d_out;

    cudaFuncSetAttribute(mlp_kernel, cudaFuncAttributeMaxDynamicSharedMemorySize, SM_BYTES);

    pool_kernel<<<BATCH / K1_ROWS, 256>>>(x, w_step, b_step);
    mlp_kernel<<<BATCH / NROWS, 512, SM_BYTES>>>(wA, bA, wB, bB, wC, bC, out);
}

// round 11
// speedup vs baseline: 1.7073x; 1.0572x over previous
#include <cuda_runtime.h>

#define BATCH     16384
#define QSEQ      1204
#define FDIM      7
#define NCHUNKS   120
#define NOFF      5
#define WINSZ     10
#define NCAT      600
#define H1DIM     128
#define H2DIM     32
#define ODIM      2

// cat scratch, k-major: g_cat[k*BATCH + b]
__device__ float g_cat[(size_t)NCAT * BATCH];

// ---------------------------------------------------------------------------
__device__ __forceinline__ unsigned long long pack2(float lo, float hi) {
    unsigned long long r;
    asm("mov.b64 %0, {%1, %2};" : "=l"(r) : "f"(lo), "f"(hi));
    return r;
}
__device__ __forceinline__ void unpack2(unsigned long long v, float& lo, float& hi) {
    asm("mov.b64 {%0, %1}, %2;" : "=f"(lo), "=f"(hi) : "l"(v));
}
__device__ __forceinline__ unsigned long long ffma2(unsigned long long a,
                                                    unsigned long long b,
                                                    unsigned long long c) {
    unsigned long long d;
    asm("fma.rn.f32x2 %0, %1, %2, %3;" : "=l"(d) : "l"(a), "l"(b), "l"(c));
    return d;
}
__device__ __forceinline__ void cp_async16(void* smem_dst, const void* gsrc) {
    unsigned s = (unsigned)__cvta_generic_to_shared(smem_dst);
    asm volatile("cp.async.ca.shared.global [%0], [%1], 16;\n" :: "r"(s), "l"(gsrc));
}
__device__ __forceinline__ void cp_commit() {
    asm volatile("cp.async.commit_group;\n" ::: "memory");
}
__device__ __forceinline__ void cp_wait2() {
    asm volatile("cp.async.wait_group 2;\n" ::: "memory");
}

// ===========================================================================
// Kernel 1: dot-7 + windowed max pool (unchanged — known good, ~62% DRAM)
// ===========================================================================
#define K1_ROWS 8
__global__ __launch_bounds__(256)
void pool_kernel(const float* __restrict__ x,
                 const float* __restrict__ w_step,
                 const float* __restrict__ b_step)
{
    __shared__ float sm_out[K1_ROWS][QSEQ];

    const int tid = threadIdx.x;
    const size_t b0 = (size_t)blockIdx.x * K1_ROWS;

    float ws[FDIM];
#pragma unroll
    for (int f = 0; f < FDIM; ++f) ws[f] = __ldg(&w_step[f]);
    const float bs = __ldg(b_step);

    for (int it = tid; it < K1_ROWS * 301; it += 256) {
        const int r  = it / 301;
        const int qd = it - r * 301;
        const float4* p = (const float4*)(x + (b0 + (size_t)r) * (QSEQ * FDIM) + qd * 28);
        float v[28];
#pragma unroll
        for (int i = 0; i < 7; ++i) {
            float4 t = p[i];
            v[i*4+0] = t.x; v[i*4+1] = t.y; v[i*4+2] = t.z; v[i*4+3] = t.w;
        }
#pragma unroll
        for (int qq = 0; qq < 4; ++qq) {
            float acc = bs;
#pragma unroll
            for (int f = 0; f < FDIM; ++f)
                acc = fmaf(v[qq*FDIM + f], ws[f], acc);
            sm_out[r][qd*4 + qq] = acc;
        }
    }
    __syncthreads();

    for (int it = tid; it < K1_ROWS * NCHUNKS; it += 256) {
        const int r = it & (K1_ROWS - 1);
        const int i = it >> 3;
        const float* o = &sm_out[r][i * WINSZ];
        float v[14];
#pragma unroll
        for (int j = 0; j < 14; ++j) v[j] = o[j];

        float common = v[4];
#pragma unroll
        for (int j = 5; j < 10; ++j) common = fmaxf(common, v[j]);
        const float P1 = v[10];
        const float P2 = fmaxf(P1, v[11]);
        const float P3 = fmaxf(P2, v[12]);
        const float P4 = fmaxf(P3, v[13]);
        const float T3 = v[3];
        const float T2 = fmaxf(v[2], T3);
        const float T1 = fmaxf(v[1], T2);
        const float T0 = fmaxf(v[0], T1);

        float m[5];
        m[0] = fmaxf(common, T0);
        m[1] = fmaxf(fmaxf(common, T1), P1);
        m[2] = fmaxf(fmaxf(common, T2), P2);
        m[3] = fmaxf(fmaxf(common, T3), P3);
        m[4] = fmaxf(common, P4);

        const size_t base = b0 + (size_t)r;
        const size_t c0 = (size_t)(i * NOFF) * BATCH + base;
#pragma unroll
        for (int o2 = 0; o2 < NOFF; ++o2)
            g_cat[c0 + (size_t)o2 * BATCH] = m[o2];
    }
}

// ===========================================================================
// Kernel 2: MLP. grid 128, 512 thr, 128 rows/CTA.
// NBUF=4 ring, ONE __syncthreads per tile; wB staged in smem for layer B.
// Thread = (lane -> 4 rows, warp -> 8 neurons): 6 LDS wf per 32 FFMA2.
// ===========================================================================
#define NROWS  128
#define KT     40
#define NTILE  15                       // 15*40 = 600
#define WA_TF  (KT * H1DIM)             // 5120 floats
#define CT_TF  (KT * NROWS)             // 5120 floats
#define BUF_F  (WA_TF + CT_TF)          // 10240 floats = 40960 B
#define NBUF   4
#define WB_F   (H1DIM * H2DIM)          // 4096 floats
#define SM_BYTES ((NBUF * BUF_F + WB_F) * 4)   // 180224 B

__global__ __launch_bounds__(512, 1)
void mlp_kernel(const float* __restrict__ wA,
                const float* __restrict__ bA,
                const float* __restrict__ wB,
                const float* __restrict__ bB,
                const float* __restrict__ wC,
                const float* __restrict__ bC,
                float* __restrict__ out)
{
    extern __shared__ float smem[];
    float* sm_h1 = smem;                    // 128*128 floats, alias after loop
    float* sm_h2 = smem + H1DIM * NROWS;    // 128*32 floats, alias (dead bufs)
    float* sm_wB = smem + NBUF * BUF_F;     // 4096 floats, persistent

    const int tid  = threadIdx.x;
    const int lane = tid & 31;
    const int w    = tid >> 5;             // 0..15
    const int j0   = w * 8;                // 8 neurons per warp
    const int r0   = lane * 4;             // 4 rows per lane
    const size_t b0 = (size_t)blockIdx.x * NROWS;

    auto load_tile = [&](int t) {
        float* wbuf = smem + (t % NBUF) * BUF_F;
        float* cbuf = wbuf + WA_TF;
        const float* wsrc = wA + (size_t)t * WA_TF;
        const size_t kof = (size_t)t * KT;
        for (int idx = tid; idx < WA_TF / 4; idx += 512)
            cp_async16(wbuf + idx * 4, wsrc + idx * 4);
        for (int idx = tid; idx < CT_TF / 4; idx += 512) {
            const int kk = idx >> 5;
            const int rc = idx & 31;
            cp_async16(cbuf + kk * NROWS + rc * 4,
                       &g_cat[(kof + kk) * BATCH + b0 + rc * 4]);
        }
        cp_commit();
    };

    // prologue: tile 0 (+ wB) in group 0; tile 1 in group 1
    {
        float* wbuf = smem;                  // tile 0
        float* cbuf = wbuf + WA_TF;
        for (int idx = tid; idx < WA_TF / 4; idx += 512)
            cp_async16(wbuf + idx * 4, wA + idx * 4);
        for (int idx = tid; idx < CT_TF / 4; idx += 512) {
            const int kk = idx >> 5;
            const int rc = idx & 31;
            cp_async16(cbuf + kk * NROWS + rc * 4,
                       &g_cat[(size_t)kk * BATCH + b0 + rc * 4]);
        }
        for (int idx = tid; idx < WB_F / 4; idx += 512)
            cp_async16(sm_wB + idx * 4, wB + idx * 4);
        cp_commit();
        load_tile(1);
    }

    // acc[n][p]: neuron j0+n, row pair (r0+2p, r0+2p+1)
    unsigned long long acc[8][2];
#pragma unroll
    for (int n = 0; n < 8; ++n) { acc[n][0] = 0ULL; acc[n][1] = 0ULL; }

    for (int t = 0; t < NTILE; ++t) {
        // load(t+2) writes buf (t+2)%4 — distinct from t%4 (being computed
        // next) and (t-1)%4 (readers all finished before the PREVIOUS
        // barrier) -> 4-deep ring makes the single-barrier schedule legal.
        if (t + 2 < NTILE) load_tile(t + 2);
        else               cp_commit();      // empty group keeps count uniform
        cp_wait2();                          // own groups: tile t landed
        __syncthreads();                     // all threads waited -> t visible

        const float* wt = smem + (t % NBUF) * BUF_F + j0;
        const float* ct = smem + (t % NBUF) * BUF_F + WA_TF + r0;
#pragma unroll 4
        for (int kk = 0; kk < KT; ++kk) {
            const ulonglong2 c2 = *(const ulonglong2*)(ct + kk * NROWS);   // 4 rows
            const float4 w0 = *(const float4*)(wt + kk * H1DIM);           // bcast
            const float4 w1 = *(const float4*)(wt + kk * H1DIM + 4);       // bcast
            const unsigned long long s0 = pack2(w0.x, w0.x);
            const unsigned long long s1 = pack2(w0.y, w0.y);
            const unsigned long long s2 = pack2(w0.z, w0.z);
            const unsigned long long s3 = pack2(w0.w, w0.w);
            const unsigned long long s4 = pack2(w1.x, w1.x);
            const unsigned long long s5 = pack2(w1.y, w1.y);
            const unsigned long long s6 = pack2(w1.z, w1.z);
            const unsigned long long s7 = pack2(w1.w, w1.w);
            acc[0][0] = ffma2(c2.x, s0, acc[0][0]);
            acc[1][0] = ffma2(c2.x, s1, acc[1][0]);
            acc[2][0] = ffma2(c2.x, s2, acc[2][0]);
            acc[3][0] = ffma2(c2.x, s3, acc[3][0]);
            acc[4][0] = ffma2(c2.x, s4, acc[4][0]);
            acc[5][0] = ffma2(c2.x, s5, acc[5][0]);
            acc[6][0] = ffma2(c2.x, s6, acc[6][0]);
            acc[7][0] = ffma2(c2.x, s7, acc[7][0]);
            acc[0][1] = ffma2(c2.y, s0, acc[0][1]);
            acc[1][1] = ffma2(c2.y, s1, acc[1][1]);
            acc[2][1] = ffma2(c2.y, s2, acc[2][1]);
            acc[3][1] = ffma2(c2.y, s3, acc[3][1]);
            acc[4][1] = ffma2(c2.y, s4, acc[4][1]);
            acc[5][1] = ffma2(c2.y, s5, acc[5][1]);
            acc[6][1] = ffma2(c2.y, s6, acc[6][1]);
            acc[7][1] = ffma2(c2.y, s7, acc[7][1]);
        }
    }

    const float4 ba0 = *(const float4*)&bA[j0];
    const float4 ba1 = *(const float4*)&bA[j0 + 4];
    __syncthreads();                     // buffers dead; alias h1

    // ---- epilogue: h1[j][r] = relu(acc + bias), layout h1[j*128 + r] ----
    {
        const float bb[8] = {ba0.x, ba0.y, ba0.z, ba0.w, ba1.x, ba1.y, ba1.z, ba1.w};
        float lo, hi;
#pragma unroll
        for (int n = 0; n < 8; ++n) {
#pragma unroll
            for (int p = 0; p < 2; ++p) {
                unpack2(acc[n][p], lo, hi);
                sm_h1[(j0 + n) * NROWS + r0 + 2*p + 0] = fmaxf(lo + bb[n], 0.0f);
                sm_h1[(j0 + n) * NROWS + r0 + 2*p + 1] = fmaxf(hi + bb[n], 0.0f);
            }
        }
    }
    __syncthreads();

    // ---- Layer B: h2[r][m] = relu(sum_j h1[j][r]*wB[j][m] + bB[m]) ----
    {
        const int m  = tid & 31;
        const int rb = (tid >> 5) * 8;           // 16 warps x 8 rows = 128
        float s[8];
#pragma unroll
        for (int r = 0; r < 8; ++r) s[r] = 0.0f;
#pragma unroll 8
        for (int j = 0; j < H1DIM; ++j) {
            const float wb = sm_wB[j * H2DIM + m];               // LDS, no L2 chain
            const float4 h0 = *(const float4*)&sm_h1[j * NROWS + rb];
            const float4 h1v = *(const float4*)&sm_h1[j * NROWS + rb + 4];
            s[0] = fmaf(h0.x, wb, s[0]);
            s[1] = fmaf(h0.y, wb, s[1]);
            s[2] = fmaf(h0.z, wb, s[2]);
            s[3] = fmaf(h0.w, wb, s[3]);
            s[4] = fmaf(h1v.x, wb, s[4]);
            s[5] = fmaf(h1v.y, wb, s[5]);
            s[6] = fmaf(h1v.z, wb, s[6]);
            s[7] = fmaf(h1v.w, wb, s[7]);
        }
        const float bm = __ldg(&bB[m]);
#pragma unroll
        for (int r = 0; r < 8; ++r)
            sm_h2[(rb + r) * H2DIM + m] = fmaxf(s[r] + bm, 0.0f);
    }
    __syncthreads();

    // ---- Layer C ----
    if (tid < NROWS * ODIM) {
        const int r = tid >> 1;
        const int c = tid & 1;
        float s = __ldg(&bC[c]);
#pragma unroll
        for (int m = 0; m < H2DIM; ++m)
            s = fmaf(sm_h2[r * H2DIM + m], __ldg(&wC[m * ODIM + c]), s);
        out[(b0 + (size_t)r) * ODIM + c] = s;
    }
}

extern "C" void kernel_launch(void* const* d_in, const int* in_sizes, int n_in,
                              void* d_out, int out_size)
{
    const float* x      = (const float*)d_in[0];
    const float* w_step = (const float*)d_in[1];
    const float* b_step = (const float*)d_in[2];
    const float* wA     = (const float*)d_in[3];
    const float* bA     = (const float*)d_in[4];
    const float* wB     = (const float*)d_in[5];
    const float* bB     = (const float*)d_in[6];
    const float* wC     = (const float*)d_in[7];
    const float* bC     = (const float*)d_in[8];
    float* out          = (float*)d_out;

    cudaFuncSetAttribute(mlp_kernel, cudaFuncAttributeMaxDynamicSharedMemorySize, SM_BYTES);

    pool_kernel<<<BATCH / K1_ROWS, 256>>>(x, w_step, b_step);
    mlp_kernel<<<BATCH / NROWS, 512, SM_BYTES>>>(wA, bA, wB, bB, wC, bC, out);
}

// round 12
// speedup vs baseline: 1.7880x; 1.0473x over previous
#include <cuda_runtime.h>

#define BATCH     16384
#define QSEQ      1204
#define FDIM      7
#define NCAT      600
#define H1DIM     128
#define H2DIM     32
#define ODIM      2

#define NROWS     128        // rows per CTA
#define KT        40         // k per tile = 8 pool-chunks
#define NTILE     15         // 15*40 = 600
#define QT        84         // queries per tile (80 + 4 lookahead)
#define F4T       147        // float4 per row-segment (588 floats)
#define DPITCH    85         // dout row pitch (85 % 32 = 21, coprime -> conflict-free)

// smem layout (floats)
#define SCR_OFF   0                         // 16 warps * 640 = 10240
#define DOUT_OFF  10240                     // 128 * 85 = 10880
#define CAT_OFF   21120                     // 2 * 40*128 = 10240
#define WA_OFF    31360                     // 2 * 40*128 = 10240
#define WB_OFF    41600                     // 4096
#define SM_F      45696
#define SM_BYTES  (SM_F * 4)                // 182784 B

// ---------------------------------------------------------------------------
__device__ __forceinline__ unsigned long long pack2(float lo, float hi) {
    unsigned long long r;
    asm("mov.b64 %0, {%1, %2};" : "=l"(r) : "f"(lo), "f"(hi));
    return r;
}
__device__ __forceinline__ void unpack2(unsigned long long v, float& lo, float& hi) {
    asm("mov.b64 {%0, %1}, %2;" : "=f"(lo), "=f"(hi) : "l"(v));
}
__device__ __forceinline__ unsigned long long ffma2(unsigned long long a,
                                                    unsigned long long b,
                                                    unsigned long long c) {
    unsigned long long d;
    asm("fma.rn.f32x2 %0, %1, %2, %3;" : "=l"(d) : "l"(a), "l"(b), "l"(c));
    return d;
}
__device__ __forceinline__ void cp_async16(void* smem_dst, const void* gsrc) {
    unsigned s = (unsigned)__cvta_generic_to_shared(smem_dst);
    asm volatile("cp.async.ca.shared.global [%0], [%1], 16;\n" :: "r"(s), "l"(gsrc));
}
__device__ __forceinline__ void cp_commit() {
    asm volatile("cp.async.commit_group;\n" ::: "memory");
}
__device__ __forceinline__ void cp_wait1() {
    asm volatile("cp.async.wait_group 1;\n" ::: "memory");
}

// ===========================================================================
// Fused kernel: pool (dot-7 + windowed max) producing cat k-tiles in smem,
// consumed by the layer-A GEMM with a one-tile skew; then layers B, C.
// ===========================================================================
__global__ __launch_bounds__(512, 1)
void fused_kernel(const float* __restrict__ x,
                  const float* __restrict__ w_step,
                  const float* __restrict__ b_step,
                  const float* __restrict__ wA,
                  const float* __restrict__ bA,
                  const float* __restrict__ wB,
                  const float* __restrict__ bB,
                  const float* __restrict__ wC,
                  const float* __restrict__ bC,
                  float* __restrict__ out)
{
    extern __shared__ float smem[];
    float* scr  = smem + SCR_OFF;     // per-warp x-stage scratch (640 floats each)
    float* dout = smem + DOUT_OFF;    // [128 rows][85] dots for current tile
    float* catb = smem + CAT_OFF;     // cat ring: stage s at + s*KT*NROWS
    float* wab  = smem + WA_OFF;      // wA ring:  stage s at + s*KT*H1DIM
    float* swB  = smem + WB_OFF;      // persistent wB
    float* h1   = smem;               // alias (dead buffers) after mainloop
    float* h2   = smem + H1DIM * NROWS;

    const int tid  = threadIdx.x;
    const int lane = tid & 31;
    const int w    = tid >> 5;                 // 0..15
    const size_t b0 = (size_t)blockIdx.x * NROWS;

    float wsv[FDIM];
#pragma unroll
    for (int f = 0; f < FDIM; ++f) wsv[f] = __ldg(&w_step[f]);
    const float bs = __ldg(b_step);

    // prologue: wB (group G_pre)
    for (int idx = tid; idx < (H1DIM * H2DIM) / 4; idx += 512)
        cp_async16(swB + idx * 4, wB + idx * 4);
    cp_commit();

    // GEMM accumulators: 8 neurons x 4 rows (R11 tile)
    unsigned long long acc[8][2];
#pragma unroll
    for (int n = 0; n < 8; ++n) { acc[n][0] = 0ULL; acc[n][1] = 0ULL; }
    const int j0  = w * 8;          // neuron base
    const int r0c = lane * 4;       // row base (consumer)

    float* myscr = scr + w * 640;
    float4 xr[5];

    for (int it = 0; it <= NTILE; ++it) {
        // ---- head: issue wA(it) one tile ahead of use ----
        if (it < NTILE) {
            const float* wsrc = wA + (size_t)it * (KT * H1DIM);
            float* wdst = wab + (it & 1) * (KT * H1DIM);
            for (int idx = tid; idx < (KT * H1DIM) / 4; idx += 512)
                cp_async16(wdst + idx * 4, wsrc + idx * 4);
        }
        cp_commit();                 // group G_it (empty at it==NTILE)
        cp_wait1();                  // G_{it-1} done -> wA(it-1) landed
        __syncthreads();             // [A] publish wA(it-1) to all threads

        if (it < NTILE) {
            // ---- producer: dots for tile it (rows w*8 .. w*8+7) ----
            const size_t xbase = (b0 + (size_t)(w * 8)) * (QSEQ * FDIM)
                               + (size_t)it * 560;
            {   // preload row 0 (coalesced float4)
                const float4* p = (const float4*)(x + xbase);
#pragma unroll
                for (int r5 = 0; r5 < 5; ++r5) {
                    const int idx = r5 * 32 + lane;
                    if (idx < F4T) xr[r5] = p[idx];
                }
            }
            for (int i = 0; i < 8; ++i) {
#pragma unroll
                for (int r5 = 0; r5 < 5; ++r5) {
                    const int idx = r5 * 32 + lane;
                    if (idx < F4T) *(float4*)(myscr + idx * 4) = xr[r5];
                }
                __syncwarp();
                if (i < 7) {         // issue next row's loads early (hide DRAM)
                    const float4* p = (const float4*)(x + xbase
                                       + (size_t)(i + 1) * (QSEQ * FDIM));
#pragma unroll
                    for (int r5 = 0; r5 < 5; ++r5) {
                        const int idx = r5 * 32 + lane;
                        if (idx < F4T) xr[r5] = p[idx];
                    }
                }
                float* drow = dout + (w * 8 + i) * DPITCH;
#pragma unroll
                for (int rd = 0; rd < 3; ++rd) {
                    const int q = rd * 32 + lane;
                    if (q < QT) {
                        const float* sq = myscr + q * 7;   // stride-7: conflict-free
                        float a = bs;
#pragma unroll
                        for (int f = 0; f < 7; ++f) a = fmaf(sq[f], wsv[f], a);
                        drow[q] = a;
                    }
                }
                __syncwarp();        // before scratch is overwritten
            }
            __syncthreads();         // [B] dout complete

            // ---- producer: pool tile it -> cat stage it&1 ----
            float* cb = catb + (it & 1) * (KT * NROWS);
#pragma unroll
            for (int itm = 0; itm < 2; ++itm) {
                const int item = itm * 512 + tid;         // 1024 items
                const int r  = item & 127;
                const int ci = item >> 7;                 // 0..7
                const float* dr = dout + r * DPITCH + ci * 10;
                float v[14];
#pragma unroll
                for (int j = 0; j < 14; ++j) v[j] = dr[j];

                float common = v[4];
#pragma unroll
                for (int j = 5; j < 10; ++j) common = fmaxf(common, v[j]);
                const float P1 = v[10];
                const float P2 = fmaxf(P1, v[11]);
                const float P3 = fmaxf(P2, v[12]);
                const float P4 = fmaxf(P3, v[13]);
                const float T3 = v[3];
                const float T2 = fmaxf(v[2], T3);
                const float T1 = fmaxf(v[1], T2);
                const float T0 = fmaxf(v[0], T1);

                const int kk0 = 5 * ci;
                cb[(kk0 + 0) * NROWS + r] = fmaxf(common, T0);
                cb[(kk0 + 1) * NROWS + r] = fmaxf(fmaxf(common, T1), P1);
                cb[(kk0 + 2) * NROWS + r] = fmaxf(fmaxf(common, T2), P2);
                cb[(kk0 + 3) * NROWS + r] = fmaxf(fmaxf(common, T3), P3);
                cb[(kk0 + 4) * NROWS + r] = fmaxf(common, P4);
            }
        }

        if (it >= 1) {
            // ---- consumer: GEMM tile it-1 (R11 inner loop) ----
            const float* wt = wab  + ((it - 1) & 1) * (KT * H1DIM) + j0;
            const float* ct = catb + ((it - 1) & 1) * (KT * NROWS) + r0c;
#pragma unroll 4
            for (int kk = 0; kk < KT; ++kk) {
                const ulonglong2 c2 = *(const ulonglong2*)(ct + kk * NROWS);
                const float4 w0 = *(const float4*)(wt + kk * H1DIM);
                const float4 w1 = *(const float4*)(wt + kk * H1DIM + 4);
                const unsigned long long s0 = pack2(w0.x, w0.x);
                const unsigned long long s1 = pack2(w0.y, w0.y);
                const unsigned long long s2 = pack2(w0.z, w0.z);
                const unsigned long long s3 = pack2(w0.w, w0.w);
                const unsigned long long s4 = pack2(w1.x, w1.x);
                const unsigned long long s5 = pack2(w1.y, w1.y);
                const unsigned long long s6 = pack2(w1.z, w1.z);
                const unsigned long long s7 = pack2(w1.w, w1.w);
                acc[0][0] = ffma2(c2.x, s0, acc[0][0]);
                acc[1][0] = ffma2(c2.x, s1, acc[1][0]);
                acc[2][0] = ffma2(c2.x, s2, acc[2][0]);
                acc[3][0] = ffma2(c2.x, s3, acc[3][0]);
                acc[4][0] = ffma2(c2.x, s4, acc[4][0]);
                acc[5][0] = ffma2(c2.x, s5, acc[5][0]);
                acc[6][0] = ffma2(c2.x, s6, acc[6][0]);
                acc[7][0] = ffma2(c2.x, s7, acc[7][0]);
                acc[0][1] = ffma2(c2.y, s0, acc[0][1]);
                acc[1][1] = ffma2(c2.y, s1, acc[1][1]);
                acc[2][1] = ffma2(c2.y, s2, acc[2][1]);
                acc[3][1] = ffma2(c2.y, s3, acc[3][1]);
                acc[4][1] = ffma2(c2.y, s4, acc[4][1]);
                acc[5][1] = ffma2(c2.y, s5, acc[5][1]);
                acc[6][1] = ffma2(c2.y, s6, acc[6][1]);
                acc[7][1] = ffma2(c2.y, s7, acc[7][1]);
            }
        }
        __syncthreads();             // [C] publish cat(it); close WAR windows
    }

    // ---- epilogue: h1 = relu(acc + bias), layout h1[j*128 + r] ----
    const float4 ba0 = *(const float4*)&bA[j0];
    const float4 ba1 = *(const float4*)&bA[j0 + 4];
    {
        const float bb[8] = {ba0.x, ba0.y, ba0.z, ba0.w, ba1.x, ba1.y, ba1.z, ba1.w};
        float lo, hi;
#pragma unroll
        for (int n = 0; n < 8; ++n) {
#pragma unroll
            for (int p = 0; p < 2; ++p) {
                unpack2(acc[n][p], lo, hi);
                h1[(j0 + n) * NROWS + r0c + 2*p + 0] = fmaxf(lo + bb[n], 0.0f);
                h1[(j0 + n) * NROWS + r0c + 2*p + 1] = fmaxf(hi + bb[n], 0.0f);
            }
        }
    }
    __syncthreads();

    // ---- Layer B: h2[r][m] = relu(sum_j h1[j][r]*wB[j][m] + bB[m]) ----
    {
        const int m  = tid & 31;
        const int rb = (tid >> 5) * 8;           // 16 warps x 8 rows = 128
        float s[8];
#pragma unroll
        for (int r = 0; r < 8; ++r) s[r] = 0.0f;
#pragma unroll 8
        for (int j = 0; j < H1DIM; ++j) {
            const float wb = swB[j * H2DIM + m];
            const float4 h0 = *(const float4*)&h1[j * NROWS + rb];
            const float4 h1v = *(const float4*)&h1[j * NROWS + rb + 4];
            s[0] = fmaf(h0.x, wb, s[0]);
            s[1] = fmaf(h0.y, wb, s[1]);
            s[2] = fmaf(h0.z, wb, s[2]);
            s[3] = fmaf(h0.w, wb, s[3]);
            s[4] = fmaf(h1v.x, wb, s[4]);
            s[5] = fmaf(h1v.y, wb, s[5]);
            s[6] = fmaf(h1v.z, wb, s[6]);
            s[7] = fmaf(h1v.w, wb, s[7]);
        }
        const float bm = __ldg(&bB[m]);
#pragma unroll
        for (int r = 0; r < 8; ++r)
            h2[(rb + r) * H2DIM + m] = fmaxf(s[r] + bm, 0.0f);
    }
    __syncthreads();

    // ---- Layer C ----
    if (tid < NROWS * ODIM) {
        const int r = tid >> 1;
        const int c = tid & 1;
        float s = __ldg(&bC[c]);
#pragma unroll
        for (int m = 0; m < H2DIM; ++m)
            s = fmaf(h2[r * H2DIM + m], __ldg(&wC[m * ODIM + c]), s);
        out[(b0 + (size_t)r) * ODIM + c] = s;
    }
}

extern "C" void kernel_launch(void* const* d_in, const int* in_sizes, int n_in,
                              void* d_out, int out_size)
{
    const float* x      = (const float*)d_in[0];
    const float* w_step = (const float*)d_in[1];
    const float* b_step = (const float*)d_in[2];
    const float* wA     = (const float*)d_in[3];
    const float* bA     = (const float*)d_in[4];
    const float* wB     = (const float*)d_in[5];
    const float* bB     = (const float*)d_in[6];
    const float* wC     = (const float*)d_in[7];
    const float* bC     = (const float*)d_in[8];
    float* out          = (float*)d_out;

    cudaFuncSetAttribute(fused_kernel, cudaFuncAttributeMaxDynamicSharedMemorySize, SM_BYTES);

    fused_kernel<<<BATCH / NROWS, 512, SM_BYTES>>>(
        x, w_step, b_step, wA, bA, wB, bB, wC, bC, out);
}

// round 13
// speedup vs baseline: 1.9080x; 1.0671x over previous
#include <cuda_runtime.h>

#define BATCH     16384
#define QSEQ      1204
#define FDIM      7
#define NCAT      600
#define H1DIM     128
#define H2DIM     32
#define ODIM      2

#define NROWS     128        // rows per CTA
#define KT        40         // k per tile = 8 pool-chunks
#define NTILE     15         // 15*40 = 600
#define QT        84         // dots per tile (80 + 4 lookahead)
#define F4T       147        // float4 per row-segment (588 floats)
#define XBUF_F    592        // padded per-warp row buffer
#define DPITCH    85         // dout row pitch

// smem layout (floats)
#define XSCR_OFF  0                       // 16 warps * 2 * 592 = 18944
#define DOUT_OFF  18944                   // 128 * 85 = 10880
#define CAT_OFF   29824                   // 2 * 40*128 = 10240
#define WA_OFF    40064                   // 2 * 40*128 = 10240
#define WB_OFF    50304                   // 4096
#define SM_F      54400
#define SM_BYTES  (SM_F * 4)              // 217600 B

// ---------------------------------------------------------------------------
__device__ __forceinline__ unsigned long long pack2(float lo, float hi) {
    unsigned long long r;
    asm("mov.b64 %0, {%1, %2};" : "=l"(r) : "f"(lo), "f"(hi));
    return r;
}
__device__ __forceinline__ void unpack2(unsigned long long v, float& lo, float& hi) {
    asm("mov.b64 {%0, %1}, %2;" : "=f"(lo), "=f"(hi) : "l"(v));
}
__device__ __forceinline__ unsigned long long ffma2(unsigned long long a,
                                                    unsigned long long b,
                                                    unsigned long long c) {
    unsigned long long d;
    asm("fma.rn.f32x2 %0, %1, %2, %3;" : "=l"(d) : "l"(a), "l"(b), "l"(c));
    return d;
}
__device__ __forceinline__ void cp_async16(void* smem_dst, const void* gsrc) {
    unsigned s = (unsigned)__cvta_generic_to_shared(smem_dst);
    asm volatile("cp.async.cg.shared.global [%0], [%1], 16;\n" :: "r"(s), "l"(gsrc));
}
__device__ __forceinline__ void cp_commit() {
    asm volatile("cp.async.commit_group;\n" ::: "memory");
}
__device__ __forceinline__ void cp_wait1() {
    asm volatile("cp.async.wait_group 1;\n" ::: "memory");
}
__device__ __forceinline__ void cp_wait0() {
    asm volatile("cp.async.wait_group 0;\n" ::: "memory");
}

// ===========================================================================
// Fused kernel: async x stream -> dots -> windowed max (per-warp) -> cat tile
// in smem ring -> layer-A GEMM -> layers B, C.  grid 128, 512 thr, 1 CTA/SM.
// ===========================================================================
__global__ __launch_bounds__(512, 1)
void fused_kernel(const float* __restrict__ x,
                  const float* __restrict__ w_step,
                  const float* __restrict__ b_step,
                  const float* __restrict__ wA,
                  const float* __restrict__ bA,
                  const float* __restrict__ wB,
                  const float* __restrict__ bB,
                  const float* __restrict__ wC,
                  const float* __restrict__ bC,
                  float* __restrict__ out)
{
    extern __shared__ float smem[];
    float* xscr = smem + XSCR_OFF;    // per-warp ping-pong x row buffers
    float* dout = smem + DOUT_OFF;    // [128][85] dots of current tile
    float* catb = smem + CAT_OFF;     // cat ring (2 stages)
    float* wab  = smem + WA_OFF;      // wA ring (2 stages)
    float* swB  = smem + WB_OFF;      // persistent wB
    float* h1   = smem;               // alias after mainloop
    float* h2   = smem + H1DIM * NROWS;

    const int tid  = threadIdx.x;
    const int lane = tid & 31;
    const int w    = tid >> 5;                 // 0..15
    const size_t b0 = (size_t)blockIdx.x * NROWS;

    float wsv[FDIM];
#pragma unroll
    for (int f = 0; f < FDIM; ++f) wsv[f] = __ldg(&w_step[f]);
    const float bs = __ldg(b_step);

    // ---- prologue group: wB + wA(0) ----
    for (int idx = tid; idx < (H1DIM * H2DIM) / 4; idx += 512)
        cp_async16(swB + idx * 4, wB + idx * 4);
    for (int idx = tid; idx < (KT * H1DIM) / 4; idx += 512)
        cp_async16(wab + idx * 4, wA + idx * 4);
    cp_commit();

    // GEMM accumulators: 8 neurons x 4 rows
    unsigned long long acc[8][2];
#pragma unroll
    for (int n = 0; n < 8; ++n) { acc[n][0] = 0ULL; acc[n][1] = 0ULL; }
    const int j0  = w * 8;
    const int r0c = lane * 4;

    float* mybuf = xscr + w * (2 * XBUF_F);
    const size_t xrow0 = (b0 + (size_t)(w * 8)) * (size_t)(QSEQ * FDIM);

    for (int it = 0; it < NTILE; ++it) {
        const size_t xoff = xrow0 + (size_t)it * 560;

        // issue x row 0 of this tile
        {
            const float* src = x + xoff;
            for (int c = lane; c < F4T; c += 32)
                cp_async16(mybuf + c * 4, src + c * 4);
            cp_commit();
        }

        for (int i = 0; i < 8; ++i) {
            if (i < 7) {
                // issue x row i+1 (and wA(it+1) piggybacked on row 1's group)
                const float* src = x + xoff + (size_t)(i + 1) * (QSEQ * FDIM);
                float* dst = mybuf + ((i + 1) & 1) * XBUF_F;
                for (int c = lane; c < F4T; c += 32)
                    cp_async16(dst + c * 4, src + c * 4);
                if (i == 0 && it + 1 < NTILE) {
                    const float* wsrc = wA + (size_t)(it + 1) * (KT * H1DIM);
                    float* wdst = wab + ((it + 1) & 1) * (KT * H1DIM);
                    for (int idx = tid; idx < (KT * H1DIM) / 4; idx += 512)
                        cp_async16(wdst + idx * 4, wsrc + idx * 4);
                }
                cp_commit();
                cp_wait1();          // all but newest group done -> row i landed
            } else {
                cp_wait0();          // last row of tile
            }
            __syncwarp();            // publish row i within warp

            // dots for row i: 84 queries, stride-7 conflict-free LDS
            const float* buf = mybuf + (i & 1) * XBUF_F;
            float* drow = dout + (w * 8 + i) * DPITCH;
#pragma unroll
            for (int rd = 0; rd < 3; ++rd) {
                const int q = rd * 32 + lane;
                if (q < QT) {
                    const float* sq = buf + q * 7;
                    float a = bs;
#pragma unroll
                    for (int f = 0; f < 7; ++f) a = fmaf(sq[f], wsv[f], a);
                    drow[q] = a;
                }
            }
            __syncwarp();            // close WAR on buf before next issue
        }

        // ---- pooling of own rows -> cat stage it&1 (no CTA barrier needed) ----
        float* cb = catb + (it & 1) * (KT * NROWS);
#pragma unroll
        for (int half = 0; half < 2; ++half) {
            const int idx = half * 32 + lane;     // 0..63
            const int rl  = idx & 7;
            const int ci  = idx >> 3;             // 0..7
            const int r   = w * 8 + rl;
            const float* dr = dout + r * DPITCH + ci * 10;
            float v[14];
#pragma unroll
            for (int j = 0; j < 14; ++j) v[j] = dr[j];

            float common = v[4];
#pragma unroll
            for (int j = 5; j < 10; ++j) common = fmaxf(common, v[j]);
            const float P1 = v[10];
            const float P2 = fmaxf(P1, v[11]);
            const float P3 = fmaxf(P2, v[12]);
            const float P4 = fmaxf(P3, v[13]);
            const float T3 = v[3];
            const float T2 = fmaxf(v[2], T3);
            const float T1 = fmaxf(v[1], T2);
            const float T0 = fmaxf(v[0], T1);

            const int k0 = 5 * ci;
            cb[(k0 + 0) * NROWS + r] = fmaxf(common, T0);
            cb[(k0 + 1) * NROWS + r] = fmaxf(fmaxf(common, T1), P1);
            cb[(k0 + 2) * NROWS + r] = fmaxf(fmaxf(common, T2), P2);
            cb[(k0 + 3) * NROWS + r] = fmaxf(fmaxf(common, T3), P3);
            cb[(k0 + 4) * NROWS + r] = fmaxf(common, P4);
        }
        __syncthreads();             // [pre-GEMM] publish cat(it) + wA(it)

        // ---- GEMM tile it ----
        const float* wt = wab  + (it & 1) * (KT * H1DIM) + j0;
        const float* ct = catb + (it & 1) * (KT * NROWS) + r0c;
#pragma unroll 4
        for (int kk = 0; kk < KT; ++kk) {
            const ulonglong2 c2 = *(const ulonglong2*)(ct + kk * NROWS);
            const float4 w0 = *(const float4*)(wt + kk * H1DIM);
            const float4 w1 = *(const float4*)(wt + kk * H1DIM + 4);
            const unsigned long long s0 = pack2(w0.x, w0.x);
            const unsigned long long s1 = pack2(w0.y, w0.y);
            const unsigned long long s2 = pack2(w0.z, w0.z);
            const unsigned long long s3 = pack2(w0.w, w0.w);
            const unsigned long long s4 = pack2(w1.x, w1.x);
            const unsigned long long s5 = pack2(w1.y, w1.y);
            const unsigned long long s6 = pack2(w1.z, w1.z);
            const unsigned long long s7 = pack2(w1.w, w1.w);
            acc[0][0] = ffma2(c2.x, s0, acc[0][0]);
            acc[1][0] = ffma2(c2.x, s1, acc[1][0]);
            acc[2][0] = ffma2(c2.x, s2, acc[2][0]);
            acc[3][0] = ffma2(c2.x, s3, acc[3][0]);
            acc[4][0] = ffma2(c2.x, s4, acc[4][0]);
            acc[5][0] = ffma2(c2.x, s5, acc[5][0]);
            acc[6][0] = ffma2(c2.x, s6, acc[6][0]);
            acc[7][0] = ffma2(c2.x, s7, acc[7][0]);
            acc[0][1] = ffma2(c2.y, s0, acc[0][1]);
            acc[1][1] = ffma2(c2.y, s1, acc[1][1]);
            acc[2][1] = ffma2(c2.y, s2, acc[2][1]);
            acc[3][1] = ffma2(c2.y, s3, acc[3][1]);
            acc[4][1] = ffma2(c2.y, s4, acc[4][1]);
            acc[5][1] = ffma2(c2.y, s5, acc[5][1]);
            acc[6][1] = ffma2(c2.y, s6, acc[6][1]);
            acc[7][1] = ffma2(c2.y, s7, acc[7][1]);
        }
        __syncthreads();             // [post-GEMM] close WAR on cat/wA rings
    }

    // ---- epilogue: h1 = relu(acc + bias), layout h1[j*128 + r] ----
    const float4 ba0 = *(const float4*)&bA[j0];
    const float4 ba1 = *(const float4*)&bA[j0 + 4];
    {
        const float bb[8] = {ba0.x, ba0.y, ba0.z, ba0.w, ba1.x, ba1.y, ba1.z, ba1.w};
        float lo, hi;
#pragma unroll
        for (int n = 0; n < 8; ++n) {
#pragma unroll
            for (int p = 0; p < 2; ++p) {
                unpack2(acc[n][p], lo, hi);
                h1[(j0 + n) * NROWS + r0c + 2*p + 0] = fmaxf(lo + bb[n], 0.0f);
                h1[(j0 + n) * NROWS + r0c + 2*p + 1] = fmaxf(hi + bb[n], 0.0f);
            }
        }
    }
    __syncthreads();

    // ---- Layer B: h2[r][m] = relu(sum_j h1[j][r]*wB[j][m] + bB[m]) ----
    {
        const int m  = tid & 31;
        const int rb = (tid >> 5) * 8;           // 16 warps x 8 rows = 128
        float s[8];
#pragma unroll
        for (int r = 0; r < 8; ++r) s[r] = 0.0f;
#pragma unroll 8
        for (int j = 0; j < H1DIM; ++j) {
            const float wb = swB[j * H2DIM + m];
            const float4 h0 = *(const float4*)&h1[j * NROWS + rb];
            const float4 h1v = *(const float4*)&h1[j * NROWS + rb + 4];
            s[0] = fmaf(h0.x, wb, s[0]);
            s[1] = fmaf(h0.y, wb, s[1]);
            s[2] = fmaf(h0.z, wb, s[2]);
            s[3] = fmaf(h0.w, wb, s[3]);
            s[4] = fmaf(h1v.x, wb, s[4]);
            s[5] = fmaf(h1v.y, wb, s[5]);
            s[6] = fmaf(h1v.z, wb, s[6]);
            s[7] = fmaf(h1v.w, wb, s[7]);
        }
        const float bm = __ldg(&bB[m]);
#pragma unroll
        for (int r = 0; r < 8; ++r)
            h2[(rb + r) * H2DIM + m] = fmaxf(s[r] + bm, 0.0f);
    }
    __syncthreads();

    // ---- Layer C ----
    if (tid < NROWS * ODIM) {
        const int r = tid >> 1;
        const int c = tid & 1;
        float s = __ldg(&bC[c]);
#pragma unroll
        for (int m = 0; m < H2DIM; ++m)
            s = fmaf(h2[r * H2DIM + m], __ldg(&wC[m * ODIM + c]), s);
        out[(b0 + (size_t)r) * ODIM + c] = s;
    }
}

extern "C" void kernel_launch(void* const* d_in, const int* in_sizes, int n_in,
                              void* d_out, int out_size)
{
    const float* x      = (const float*)d_in[0];
    const float* w_step = (const float*)d_in[1];
    const float* b_step = (const float*)d_in[2];
    const float* wA     = (const float*)d_in[3];
    const float* bA     = (const float*)d_in[4];
    const float* wB     = (const float*)d_in[5];
    const float* bB     = (const float*)d_in[6];
    const float* wC     = (const float*)d_in[7];
    const float* bC     = (const float*)d_in[8];
    float* out          = (float*)d_out;

    cudaFuncSetAttribute(fused_kernel, cudaFuncAttributeMaxDynamicSharedMemorySize, SM_BYTES);

    fused_kernel<<<BATCH / NROWS, 512, SM_BYTES>>>(
        x, w_step, b_step, wA, bA, wB, bB, wC, bC, out);
}

// round 14
// speedup vs baseline: 2.1457x; 1.1245x over previous
#include <cuda_runtime.h>

#define BATCH     16384
#define QSEQ      1204
#define FDIM      7
#define NCAT      600
#define H1DIM     128
#define H2DIM     32
#define ODIM      2

#define NROWS     128        // rows per CTA
#define KT        40         // k per tile = 8 pool-chunks
#define NTILE     15         // 15*40 = 600
#define SEGS      (NTILE * 8)  // 120 row-segments per warp
#define QT        84         // dots per segment (80 + 4 lookahead)
#define F4T       147        // float4 per row-segment (588 floats)
#define XBUF_F    592        // padded per-warp row buffer (floats)
#define CPITCH    132        // cat tile pitch (conflict-free pool stores)

// smem layout (floats)
#define XSCR_OFF  0                         // 16 warps * 3 * 592 = 28416
#define DROW_OFF  28416                     // 16 * 96 = 1536
#define CAT_OFF   29952                     // 2 * 40*132 = 10560
#define WA_OFF    40512                     // 2 * 40*128 = 10240
#define WB_OFF    50752                     // 4096
#define SM_F      54848
#define SM_BYTES  (SM_F * 4)                // 219392 B

// ---------------------------------------------------------------------------
__device__ __forceinline__ unsigned long long pack2(float lo, float hi) {
    unsigned long long r;
    asm("mov.b64 %0, {%1, %2};" : "=l"(r) : "f"(lo), "f"(hi));
    return r;
}
__device__ __forceinline__ void unpack2(unsigned long long v, float& lo, float& hi) {
    asm("mov.b64 {%0, %1}, %2;" : "=f"(lo), "=f"(hi) : "l"(v));
}
__device__ __forceinline__ unsigned long long ffma2(unsigned long long a,
                                                    unsigned long long b,
                                                    unsigned long long c) {
    unsigned long long d;
    asm("fma.rn.f32x2 %0, %1, %2, %3;" : "=l"(d) : "l"(a), "l"(b), "l"(c));
    return d;
}
__device__ __forceinline__ void cp_async16(void* smem_dst, const void* gsrc) {
    unsigned s = (unsigned)__cvta_generic_to_shared(smem_dst);
    asm volatile("cp.async.cg.shared.global [%0], [%1], 16;\n" :: "r"(s), "l"(gsrc));
}
__device__ __forceinline__ void cp_commit() {
    asm volatile("cp.async.commit_group;\n" ::: "memory");
}
__device__ __forceinline__ void cp_wait2() {
    asm volatile("cp.async.wait_group 2;\n" ::: "memory");
}

// ===========================================================================
// Fused kernel, 3-deep async x ring:
//   seg pipeline (issue s+2 / wait s) -> dots -> per-row pool -> cat ring
//   -> layer-A GEMM per k-tile -> layers B, C.
// grid 128, 512 thr, 1 CTA/SM.
// ===========================================================================
__global__ __launch_bounds__(512, 1)
void fused_kernel(const float* __restrict__ x,
                  const float* __restrict__ w_step,
                  const float* __restrict__ b_step,
                  const float* __restrict__ wA,
                  const float* __restrict__ bA,
                  const float* __restrict__ wB,
                  const float* __restrict__ bB,
                  const float* __restrict__ wC,
                  const float* __restrict__ bC,
                  float* __restrict__ out)
{
    extern __shared__ float smem[];
    float* xscr = smem + XSCR_OFF;    // per-warp 3-deep x ring
    float* drow = smem + DROW_OFF;    // per-warp dot row (96 pitch)
    float* catb = smem + CAT_OFF;     // cat ring (2 stages, pitch 132)
    float* wab  = smem + WA_OFF;      // wA ring (2 stages, pitch 128)
    float* swB  = smem + WB_OFF;      // persistent wB
    float* h1   = smem;               // alias after mainloop
    float* h2   = smem + H1DIM * NROWS;

    const int tid  = threadIdx.x;
    const int lane = tid & 31;
    const int w    = tid >> 5;                 // 0..15
    const size_t b0 = (size_t)blockIdx.x * NROWS;

    float wsv[FDIM];
#pragma unroll
    for (int f = 0; f < FDIM; ++f) wsv[f] = __ldg(&w_step[f]);
    const float bs = __ldg(b_step);

    float* mybuf = xscr + w * (3 * XBUF_F);
    float* mydr  = drow + w * 96;
    const size_t xrow0 = (b0 + (size_t)(w * 8)) * (size_t)(QSEQ * FDIM);

    // seg s -> tile s>>3, row s&7; issues one commit-group
    auto issue_seg = [&](int s) {
        const int its = s >> 3;
        const int is  = s & 7;
        const float* src = x + xrow0 + (size_t)its * 560
                         + (size_t)is * (QSEQ * FDIM);
        float* dst = mybuf + (s % 3) * XBUF_F;
#pragma unroll
        for (int c0 = 0; c0 < 5; ++c0) {
            const int c = c0 * 32 + lane;
            if (c < F4T) cp_async16(dst + c * 4, src + c * 4);
        }
    };

    // ---- prologue: group A = {wB, wA(0)}; then seg 0, seg 1 ----
    for (int idx = tid; idx < (H1DIM * H2DIM) / 4; idx += 512)
        cp_async16(swB + idx * 4, wB + idx * 4);
    for (int idx = tid; idx < (KT * H1DIM) / 4; idx += 512)
        cp_async16(wab + idx * 4, wA + idx * 4);
    cp_commit();
    issue_seg(0); cp_commit();
    issue_seg(1); cp_commit();

    // GEMM accumulators: 8 neurons x 4 rows
    unsigned long long acc[8][2];
#pragma unroll
    for (int n = 0; n < 8; ++n) { acc[n][0] = 0ULL; acc[n][1] = 0ULL; }
    const int j0  = w * 8;
    const int r0c = lane * 4;

    for (int it = 0; it < NTILE; ++it) {
        float* cb = catb + (it & 1) * (KT * CPITCH);

        for (int i = 0; i < 8; ++i) {
            const int s = it * 8 + i;
            // issue seg s+2 (+ wA(it+1) piggyback at tile starts)
            if (s + 2 < SEGS) {
                issue_seg(s + 2);
                if (i == 0 && it + 1 < NTILE) {
                    const float* wsrc = wA + (size_t)(it + 1) * (KT * H1DIM);
                    float* wdst = wab + ((it + 1) & 1) * (KT * H1DIM);
                    for (int idx = tid; idx < (KT * H1DIM) / 4; idx += 512)
                        cp_async16(wdst + idx * 4, wsrc + idx * 4);
                }
            }
            cp_commit();             // uniform: one group per seg slot
            cp_wait2();              // seg s (and older groups) landed
            __syncwarp();

            // dots for row i of tile it (84 queries), stride-7 LDS
            const float* buf = mybuf + (s % 3) * XBUF_F;
#pragma unroll
            for (int rd = 0; rd < 3; ++rd) {
                const int q = rd * 32 + lane;
                if (q < QT) {
                    const float* sq = buf + q * 7;
                    float a = bs;
#pragma unroll
                    for (int f = 0; f < 7; ++f) a = fmaf(sq[f], wsv[f], a);
                    mydr[q] = a;
                }
            }
            __syncwarp();

            // per-row pooling: lanes 0..7 handle chunk ci
            if (lane < 8) {
                const int ci = lane;
                const float* dr = mydr + ci * 10;
                float v[14];
#pragma unroll
                for (int j = 0; j < 14; ++j) v[j] = dr[j];

                float common = v[4];
#pragma unroll
                for (int j = 5; j < 10; ++j) common = fmaxf(common, v[j]);
                const float P1 = v[10];
                const float P2 = fmaxf(P1, v[11]);
                const float P3 = fmaxf(P2, v[12]);
                const float P4 = fmaxf(P3, v[13]);
                const float T3 = v[3];
                const float T2 = fmaxf(v[2], T3);
                const float T1 = fmaxf(v[1], T2);
                const float T0 = fmaxf(v[0], T1);

                const int r  = w * 8 + i;
                const int k0 = 5 * ci;
                cb[(k0 + 0) * CPITCH + r] = fmaxf(common, T0);
                cb[(k0 + 1) * CPITCH + r] = fmaxf(fmaxf(common, T1), P1);
                cb[(k0 + 2) * CPITCH + r] = fmaxf(fmaxf(common, T2), P2);
                cb[(k0 + 3) * CPITCH + r] = fmaxf(fmaxf(common, T3), P3);
                cb[(k0 + 4) * CPITCH + r] = fmaxf(common, P4);
            }
            __syncwarp();            // drow WAR before next row's dots
        }
        __syncthreads();             // [pre-GEMM] publish cat(it) + wA(it)

        // ---- GEMM tile it ----
        const float* wt = wab  + (it & 1) * (KT * H1DIM) + j0;
        const float* ct = catb + (it & 1) * (KT * CPITCH) + r0c;
#pragma unroll 4
        for (int kk = 0; kk < KT; ++kk) {
            const ulonglong2 c2 = *(const ulonglong2*)(ct + kk * CPITCH);
            const float4 w0 = *(const float4*)(wt + kk * H1DIM);
            const float4 w1 = *(const float4*)(wt + kk * H1DIM + 4);
            const unsigned long long s0 = pack2(w0.x, w0.x);
            const unsigned long long s1 = pack2(w0.y, w0.y);
            const unsigned long long s2 = pack2(w0.z, w0.z);
            const unsigned long long s3 = pack2(w0.w, w0.w);
            const unsigned long long s4 = pack2(w1.x, w1.x);
            const unsigned long long s5 = pack2(w1.y, w1.y);
            const unsigned long long s6 = pack2(w1.z, w1.z);
            const unsigned long long s7 = pack2(w1.w, w1.w);
            acc[0][0] = ffma2(c2.x, s0, acc[0][0]);
            acc[1][0] = ffma2(c2.x, s1, acc[1][0]);
            acc[2][0] = ffma2(c2.x, s2, acc[2][0]);
            acc[3][0] = ffma2(c2.x, s3, acc[3][0]);
            acc[4][0] = ffma2(c2.x, s4, acc[4][0]);
            acc[5][0] = ffma2(c2.x, s5, acc[5][0]);
            acc[6][0] = ffma2(c2.x, s6, acc[6][0]);
            acc[7][0] = ffma2(c2.x, s7, acc[7][0]);
            acc[0][1] = ffma2(c2.y, s0, acc[0][1]);
            acc[1][1] = ffma2(c2.y, s1, acc[1][1]);
            acc[2][1] = ffma2(c2.y, s2, acc[2][1]);
            acc[3][1] = ffma2(c2.y, s3, acc[3][1]);
            acc[4][1] = ffma2(c2.y, s4, acc[4][1]);
            acc[5][1] = ffma2(c2.y, s5, acc[5][1]);
            acc[6][1] = ffma2(c2.y, s6, acc[6][1]);
            acc[7][1] = ffma2(c2.y, s7, acc[7][1]);
        }
        __syncthreads();             // [post-GEMM] close WAR on cat/wA rings
    }

    // ---- epilogue: h1 = relu(acc + bias), layout h1[j*128 + r] ----
    const float4 ba0 = *(const float4*)&bA[j0];
    const float4 ba1 = *(const float4*)&bA[j0 + 4];
    {
        const float bb[8] = {ba0.x, ba0.y, ba0.z, ba0.w, ba1.x, ba1.y, ba1.z, ba1.w};
        float lo, hi;
#pragma unroll
        for (int n = 0; n < 8; ++n) {
#pragma unroll
            for (int p = 0; p < 2; ++p) {
                unpack2(acc[n][p], lo, hi);
                h1[(j0 + n) * NROWS + r0c + 2*p + 0] = fmaxf(lo + bb[n], 0.0f);
                h1[(j0 + n) * NROWS + r0c + 2*p + 1] = fmaxf(hi + bb[n], 0.0f);
            }
        }
    }
    __syncthreads();

    // ---- Layer B ----
    {
        const int m  = tid & 31;
        const int rb = (tid >> 5) * 8;           // 16 warps x 8 rows = 128
        float s[8];
#pragma unroll
        for (int r = 0; r < 8; ++r) s[r] = 0.0f;
#pragma unroll 8
        for (int j = 0; j < H1DIM; ++j) {
            const float wb = swB[j * H2DIM + m];
            const float4 h0 = *(const float4*)&h1[j * NROWS + rb];
            const float4 h1v = *(const float4*)&h1[j * NROWS + rb + 4];
            s[0] = fmaf(h0.x, wb, s[0]);
            s[1] = fmaf(h0.y, wb, s[1]);
            s[2] = fmaf(h0.z, wb, s[2]);
            s[3] = fmaf(h0.w, wb, s[3]);
            s[4] = fmaf(h1v.x, wb, s[4]);
            s[5] = fmaf(h1v.y, wb, s[5]);
            s[6] = fmaf(h1v.z, wb, s[6]);
            s[7] = fmaf(h1v.w, wb, s[7]);
        }
        const float bm = __ldg(&bB[m]);
#pragma unroll
        for (int r = 0; r < 8; ++r)
            h2[(rb + r) * H2DIM + m] = fmaxf(s[r] + bm, 0.0f);
    }
    __syncthreads();

    // ---- Layer C ----
    if (tid < NROWS * ODIM) {
        const int r = tid >> 1;
        const int c = tid & 1;
        float s = __ldg(&bC[c]);
#pragma unroll
        for (int m = 0; m < H2DIM; ++m)
            s = fmaf(h2[r * H2DIM + m], __ldg(&wC[m * ODIM + c]), s);
        out[(b0 + (size_t)r) * ODIM + c] = s;
    }
}

extern "C" void kernel_launch(void* const* d_in, const int* in_sizes, int n_in,
                              void* d_out, int out_size)
{
    const float* x      = (const float*)d_in[0];
    const float* w_step = (const float*)d_in[1];
    const float* b_step = (const float*)d_in[2];
    const float* wA     = (const float*)d_in[3];
    const float* bA     = (const float*)d_in[4];
    const float* wB     = (const float*)d_in[5];
    const float* bB     = (const float*)d_in[6];
    const float* wC     = (const float*)d_in[7];
    const float* bC     = (const float*)d_in[8];
    float* out          = (float*)d_out;

    cudaFuncSetAttribute(fused_kernel, cudaFuncAttributeMaxDynamicSharedMemorySize, SM_BYTES);

    fused_kernel<<<BATCH / NROWS, 512, SM_BYTES>>>(
        x, w_step, b_step, wA, bA, wB, bB, wC, bC, out);
}

// round 15
// speedup vs baseline: 2.3454x; 1.0931x over previous
#include <cuda_runtime.h>

#define BATCH     16384
#define QSEQ      1204
#define FDIM      7
#define NCAT      600
#define H1DIM     128
#define H2DIM     32
#define ODIM      2

#define NROWS     128        // rows per CTA
#define KT        40         // k per tile = 8 pool-chunks
#define NTILE     15         // 15*40 = 600
#define SEGS      (NTILE * 8)  // 120 row-segments per warp
#define QT        84         // dots per segment (80 + 4 lookahead)
#define F4T       147        // float4 per row-segment (588 floats)
#define XBUF_F    592        // padded per-warp row buffer (floats)
#define CPITCH    132        // cat tile pitch
#define KCHUNK    5          // GEMM k-steps interleaved per row iteration

// smem layout (floats)
#define XSCR_OFF  0                         // 16 warps * 3 * 592 = 28416
#define DROW_OFF  28416                     // 16 * 96 = 1536
#define CAT_OFF   29952                     // 2 * 40*132 = 10560
#define WA_OFF    40512                     // 2 * 40*128 = 10240
#define WB_OFF    50752                     // 4096
#define SM_F      54848
#define SM_BYTES  (SM_F * 4)                // 219392 B

// ---------------------------------------------------------------------------
__device__ __forceinline__ unsigned long long pack2(float lo, float hi) {
    unsigned long long r;
    asm("mov.b64 %0, {%1, %2};" : "=l"(r) : "f"(lo), "f"(hi));
    return r;
}
__device__ __forceinline__ void unpack2(unsigned long long v, float& lo, float& hi) {
    asm("mov.b64 {%0, %1}, %2;" : "=f"(lo), "=f"(hi) : "l"(v));
}
__device__ __forceinline__ unsigned long long ffma2(unsigned long long a,
                                                    unsigned long long b,
                                                    unsigned long long c) {
    unsigned long long d;
    asm("fma.rn.f32x2 %0, %1, %2, %3;" : "=l"(d) : "l"(a), "l"(b), "l"(c));
    return d;
}
__device__ __forceinline__ void cp_async16(void* smem_dst, const void* gsrc) {
    unsigned s = (unsigned)__cvta_generic_to_shared(smem_dst);
    asm volatile("cp.async.cg.shared.global [%0], [%1], 16;\n" :: "r"(s), "l"(gsrc));
}
__device__ __forceinline__ void cp_commit() {
    asm volatile("cp.async.commit_group;\n" ::: "memory");
}
__device__ __forceinline__ void cp_wait2() {
    asm volatile("cp.async.wait_group 2;\n" ::: "memory");
}

// ===========================================================================
// Fused kernel, interleaved producer/GEMM:
// row iteration i of tile it:  issue seg s+2 -> wait seg s -> dots -> pool
//                              -> 5 GEMM k-steps of tile it-1.
// ONE CTA barrier per tile; tail GEMM for the last tile. grid 128, 512 thr.
// ===========================================================================
__global__ __launch_bounds__(512, 1)
void fused_kernel(const float* __restrict__ x,
                  const float* __restrict__ w_step,
                  const float* __restrict__ b_step,
                  const float* __restrict__ wA,
                  const float* __restrict__ bA,
                  const float* __restrict__ wB,
                  const float* __restrict__ bB,
                  const float* __restrict__ wC,
                  const float* __restrict__ bC,
                  float* __restrict__ out)
{
    extern __shared__ float smem[];
    float* xscr = smem + XSCR_OFF;    // per-warp 3-deep x ring
    float* drow = smem + DROW_OFF;    // per-warp dot row (96 pitch)
    float* catb = smem + CAT_OFF;     // cat ring (2 stages, pitch 132)
    float* wab  = smem + WA_OFF;      // wA ring (2 stages, pitch 128)
    float* swB  = smem + WB_OFF;      // persistent wB
    float* h1   = smem;               // alias after mainloop
    float* h2   = smem + H1DIM * NROWS;

    const int tid  = threadIdx.x;
    const int lane = tid & 31;
    const int w    = tid >> 5;                 // 0..15
    const size_t b0 = (size_t)blockIdx.x * NROWS;

    float wsv[FDIM];
#pragma unroll
    for (int f = 0; f < FDIM; ++f) wsv[f] = __ldg(&w_step[f]);
    const float bs = __ldg(b_step);

    float* mybuf = xscr + w * (3 * XBUF_F);
    float* mydr  = drow + w * 96;
    const size_t xrow0 = (b0 + (size_t)(w * 8)) * (size_t)(QSEQ * FDIM);

    auto issue_seg = [&](int s) {
        const int its = s >> 3;
        const int is  = s & 7;
        const float* src = x + xrow0 + (size_t)its * 560
                         + (size_t)is * (QSEQ * FDIM);
        float* dst = mybuf + (s % 3) * XBUF_F;
#pragma unroll
        for (int c0 = 0; c0 < 5; ++c0) {
            const int c = c0 * 32 + lane;
            if (c < F4T) cp_async16(dst + c * 4, src + c * 4);
        }
    };

    // ---- prologue: group = {wB, wA(0)}; then seg 0, seg 1 ----
    for (int idx = tid; idx < (H1DIM * H2DIM) / 4; idx += 512)
        cp_async16(swB + idx * 4, wB + idx * 4);
    for (int idx = tid; idx < (KT * H1DIM) / 4; idx += 512)
        cp_async16(wab + idx * 4, wA + idx * 4);
    cp_commit();
    issue_seg(0); cp_commit();
    issue_seg(1); cp_commit();

    // GEMM accumulators: 8 neurons x 4 rows
    unsigned long long acc[8][2];
#pragma unroll
    for (int n = 0; n < 8; ++n) { acc[n][0] = 0ULL; acc[n][1] = 0ULL; }
    const int j0  = w * 8;
    const int r0c = lane * 4;

    // one GEMM k-chunk of tile tg (ring stage tg&1), kk in [k0, k0+KCHUNK)
    auto gemm_chunk = [&](int tg, int k0) {
        const float* wt = wab  + (tg & 1) * (KT * H1DIM) + j0;
        const float* ct = catb + (tg & 1) * (KT * CPITCH) + r0c;
#pragma unroll
        for (int kq = 0; kq < KCHUNK; ++kq) {
            const int kk = k0 + kq;
            const ulonglong2 c2 = *(const ulonglong2*)(ct + kk * CPITCH);
            const float4 w0 = *(const float4*)(wt + kk * H1DIM);
            const float4 w1 = *(const float4*)(wt + kk * H1DIM + 4);
            const unsigned long long s0 = pack2(w0.x, w0.x);
            const unsigned long long s1 = pack2(w0.y, w0.y);
            const unsigned long long s2 = pack2(w0.z, w0.z);
            const unsigned long long s3 = pack2(w0.w, w0.w);
            const unsigned long long s4 = pack2(w1.x, w1.x);
            const unsigned long long s5 = pack2(w1.y, w1.y);
            const unsigned long long s6 = pack2(w1.z, w1.z);
            const unsigned long long s7 = pack2(w1.w, w1.w);
            acc[0][0] = ffma2(c2.x, s0, acc[0][0]);
            acc[1][0] = ffma2(c2.x, s1, acc[1][0]);
            acc[2][0] = ffma2(c2.x, s2, acc[2][0]);
            acc[3][0] = ffma2(c2.x, s3, acc[3][0]);
            acc[4][0] = ffma2(c2.x, s4, acc[4][0]);
            acc[5][0] = ffma2(c2.x, s5, acc[5][0]);
            acc[6][0] = ffma2(c2.x, s6, acc[6][0]);
            acc[7][0] = ffma2(c2.x, s7, acc[7][0]);
            acc[0][1] = ffma2(c2.y, s0, acc[0][1]);
            acc[1][1] = ffma2(c2.y, s1, acc[1][1]);
            acc[2][1] = ffma2(c2.y, s2, acc[2][1]);
            acc[3][1] = ffma2(c2.y, s3, acc[3][1]);
            acc[4][1] = ffma2(c2.y, s4, acc[4][1]);
            acc[5][1] = ffma2(c2.y, s5, acc[5][1]);
            acc[6][1] = ffma2(c2.y, s6, acc[6][1]);
            acc[7][1] = ffma2(c2.y, s7, acc[7][1]);
        }
    };

    for (int it = 0; it < NTILE; ++it) {
        float* cb = catb + (it & 1) * (KT * CPITCH);

        for (int i = 0; i < 8; ++i) {
            const int s = it * 8 + i;
            // issue seg s+2; wA(it) piggybacked at i==0 (it>=1)
            if (s + 2 < SEGS) {
                issue_seg(s + 2);
                if (i == 0 && it >= 1) {
                    const float* wsrc = wA + (size_t)it * (KT * H1DIM);
                    float* wdst = wab + (it & 1) * (KT * H1DIM);
                    for (int idx = tid; idx < (KT * H1DIM) / 4; idx += 512)
                        cp_async16(wdst + idx * 4, wsrc + idx * 4);
                }
            }
            cp_commit();             // uniform: one group per seg slot
            cp_wait2();              // seg s landed
            __syncwarp();

            // dots for row i of tile it (84 queries), stride-7 LDS
            const float* buf = mybuf + (s % 3) * XBUF_F;
#pragma unroll
            for (int rd = 0; rd < 3; ++rd) {
                const int q = rd * 32 + lane;
                if (q < QT) {
                    const float* sq = buf + q * 7;
                    float a = bs;
#pragma unroll
                    for (int f = 0; f < 7; ++f) a = fmaf(sq[f], wsv[f], a);
                    mydr[q] = a;
                }
            }
            __syncwarp();

            // per-row pooling: lanes 0..7 handle chunk ci
            if (lane < 8) {
                const int ci = lane;
                const float* dr = mydr + ci * 10;
                float v[14];
#pragma unroll
                for (int j = 0; j < 14; ++j) v[j] = dr[j];

                float common = v[4];
#pragma unroll
                for (int j = 5; j < 10; ++j) common = fmaxf(common, v[j]);
                const float P1 = v[10];
                const float P2 = fmaxf(P1, v[11]);
                const float P3 = fmaxf(P2, v[12]);
                const float P4 = fmaxf(P3, v[13]);
                const float T3 = v[3];
                const float T2 = fmaxf(v[2], T3);
                const float T1 = fmaxf(v[1], T2);
                const float T0 = fmaxf(v[0], T1);

                const int r  = w * 8 + i;
                const int k0 = 5 * ci;
                cb[(k0 + 0) * CPITCH + r] = fmaxf(common, T0);
                cb[(k0 + 1) * CPITCH + r] = fmaxf(fmaxf(common, T1), P1);
                cb[(k0 + 2) * CPITCH + r] = fmaxf(fmaxf(common, T2), P2);
                cb[(k0 + 3) * CPITCH + r] = fmaxf(fmaxf(common, T3), P3);
                cb[(k0 + 4) * CPITCH + r] = fmaxf(common, P4);
            }
            __syncwarp();            // drow WAR before next row's dots

            // ---- interleaved GEMM: 5 k-steps of tile it-1 ----
            if (it >= 1) gemm_chunk(it - 1, i * KCHUNK);
        }
        __syncthreads();             // publish cat(it)+wA(it); ring WAR closed
    }

    // ---- tail GEMM: tile NTILE-1, all 40 k-steps ----
#pragma unroll
    for (int i = 0; i < 8; ++i) gemm_chunk(NTILE - 1, i * KCHUNK);

    // ---- epilogue: h1 = relu(acc + bias), layout h1[j*128 + r] ----
    const float4 ba0 = *(const float4*)&bA[j0];
    const float4 ba1 = *(const float4*)&bA[j0 + 4];
    {
        const float bb[8] = {ba0.x, ba0.y, ba0.z, ba0.w, ba1.x, ba1.y, ba1.z, ba1.w};
        float lo, hi;
#pragma unroll
        for (int n = 0; n < 8; ++n) {
#pragma unroll
            for (int p = 0; p < 2; ++p) {
                unpack2(acc[n][p], lo, hi);
                h1[(j0 + n) * NROWS + r0c + 2*p + 0] = fmaxf(lo + bb[n], 0.0f);
                h1[(j0 + n) * NROWS + r0c + 2*p + 1] = fmaxf(hi + bb[n], 0.0f);
            }
        }
    }
    __syncthreads();

    // ---- Layer B ----
    {
        const int m  = tid & 31;
        const int rb = (tid >> 5) * 8;           // 16 warps x 8 rows = 128
        float s[8];
#pragma unroll
        for (int r = 0; r < 8; ++r) s[r] = 0.0f;
#pragma unroll 8
        for (int j = 0; j < H1DIM; ++j) {
            const float wb = swB[j * H2DIM + m];
            const float4 h0 = *(const float4*)&h1[j * NROWS + rb];
            const float4 h1v = *(const float4*)&h1[j * NROWS + rb + 4];
            s[0] = fmaf(h0.x, wb, s[0]);
            s[1] = fmaf(h0.y, wb, s[1]);
            s[2] = fmaf(h0.z, wb, s[2]);
            s[3] = fmaf(h0.w, wb, s[3]);
            s[4] = fmaf(h1v.x, wb, s[4]);
            s[5] = fmaf(h1v.y, wb, s[5]);
            s[6] = fmaf(h1v.z, wb, s[6]);
            s[7] = fmaf(h1v.w, wb, s[7]);
        }
        const float bm = __ldg(&bB[m]);
#pragma unroll
        for (int r = 0; r < 8; ++r)
            h2[(rb + r) * H2DIM + m] = fmaxf(s[r] + bm, 0.0f);
    }
    __syncthreads();

    // ---- Layer C ----
    if (tid < NROWS * ODIM) {
        const int r = tid >> 1;
        const int c = tid & 1;
        float s = __ldg(&bC[c]);
#pragma unroll
        for (int m = 0; m < H2DIM; ++m)
            s = fmaf(h2[r * H2DIM + m], __ldg(&wC[m * ODIM + c]), s);
        out[(b0 + (size_t)r) * ODIM + c] = s;
    }
}

extern "C" void kernel_launch(void* const* d_in, const int* in_sizes, int n_in,
                              void* d_out, int out_size)
{
    const float* x      = (const float*)d_in[0];
    const float* w_step = (const float*)d_in[1];
    const float* b_step = (const float*)d_in[2];
    const float* wA     = (const float*)d_in[3];
    const float* bA     = (const float*)d_in[4];
    const float* wB     = (const float*)d_in[5];
    const float* bB     = (const float*)d_in[6];
    const float* wC     = (const float*)d_in[7];
    const float* bC     = (const float*)d_in[8];
    float* out          = (float*)d_out;

    cudaFuncSetAttribute(fused_kernel, cudaFuncAttributeMaxDynamicSharedMemorySize, SM_BYTES);

    fused_kernel<<<BATCH / NROWS, 512, SM_BYTES>>>(
        x, w_step, b_step, wA, bA, wB, bB, wC, bC, out);
}